// round 4
// baseline (speedup 1.0000x reference)
#include <cuda_runtime.h>
#include <cstdint>

#define NN      50000
#define NE      800000
#define NMSG    200
#define NMSGP   224          // padded row (7 x 128B lines)
#define NF4     56           // NMSGP/4
#define EPB     512          // edges per block (== blockDim)
#define PADF4   9            // sB row stride in float4 (odd -> conflict-free)

// ---------------------------------------------------------------------------
// Static device scratch
// ---------------------------------------------------------------------------
__device__ __align__(16) float g_x0[NN * 30];
__device__ __align__(16) float g_x1[NN * 30];
__device__ __align__(16) float g_A [NN * NMSGP];
__device__ __align__(16) float g_B [NN * NMSGP];
__device__ int g_is64;
__device__ int g_cnt[NN];
__device__ int g_ofs[NN];
__device__ int g_bsum[64];
__device__ int g_ssrc[NE];
__device__ int g_sdst[NE];
__device__ __align__(8) float2 g_sw[NE];

// ---------------------------------------------------------------------------
// Packed f32x2 helpers
// ---------------------------------------------------------------------------
typedef unsigned long long u64;
__device__ __forceinline__ u64 fma2(u64 a, u64 b, u64 c) {
    u64 d; asm("fma.rn.f32x2 %0, %1, %2, %3;" : "=l"(d) : "l"(a), "l"(b), "l"(c)); return d;
}
__device__ __forceinline__ u64 pack2(float x) {
    u64 d; asm("mov.b64 %0, {%1, %1};" : "=l"(d) : "f"(x)); return d;
}
__device__ __forceinline__ float2 unpack2(u64 a) {
    float2 f; asm("mov.b64 {%0, %1}, %2;" : "=f"(f.x), "=f"(f.y) : "l"(a)); return f;
}

// ---------------------------------------------------------------------------
// Edge dtype detection (int64 per reference vs int32 if JAX x64 disabled)
// ---------------------------------------------------------------------------
__global__ void detect_edges_kernel(const long long* __restrict__ e64) {
    if (threadIdx.x == 0 && blockIdx.x == 0) {
        int ok = 1;
        for (int i = 0; i < 16; i++) {
            long long v = e64[i];
            if (v < 0 || v >= NN) ok = 0;
        }
        g_is64 = ok;
    }
}
__device__ __forceinline__ int load_idx(const void* edges, long long pos, bool is64) {
    if (is64) return (int)((const long long*)edges)[pos];
    return ((const int*)edges)[pos];
}

// ---------------------------------------------------------------------------
// Counting sort by dst
// ---------------------------------------------------------------------------
__global__ void zero_hist_kernel(int N) {
    int i = blockIdx.x * blockDim.x + threadIdx.x;
    if (i < N) g_cnt[i] = 0;
}
__global__ void hist_kernel(const void* __restrict__ edges, int E) {
    int e = blockIdx.x * blockDim.x + threadIdx.x;
    if (e >= E) return;
    bool is64 = (g_is64 != 0);
    atomicAdd(&g_cnt[load_idx(edges, (long long)E + e, is64)], 1);
}
__global__ void scan1_kernel(int N) {
    __shared__ int s[1024];
    int i = blockIdx.x * 1024 + threadIdx.x;
    int v = (i < N) ? g_cnt[i] : 0;
    s[threadIdx.x] = v;
    __syncthreads();
    for (int off = 1; off < 1024; off <<= 1) {
        int t = (threadIdx.x >= (unsigned)off) ? s[threadIdx.x - off] : 0;
        __syncthreads();
        s[threadIdx.x] += t;
        __syncthreads();
    }
    if (i < N) g_ofs[i] = s[threadIdx.x] - v;           // exclusive within block
    if (threadIdx.x == 1023) g_bsum[blockIdx.x] = s[1023];
}
__global__ void scan2_kernel(int nb) {
    if (threadIdx.x == 0 && blockIdx.x == 0) {
        int acc = 0;
        for (int b = 0; b < nb; b++) { int t = g_bsum[b]; g_bsum[b] = acc; acc += t; }
    }
}
__global__ void scan3_kernel(int N) {
    int i = blockIdx.x * 1024 + threadIdx.x;
    if (i < N) g_ofs[i] += g_bsum[blockIdx.x];
}
__global__ void scatter_kernel(const void* __restrict__ edges,
                               const float* __restrict__ ea, int E) {
    int e = blockIdx.x * blockDim.x + threadIdx.x;
    if (e >= E) return;
    bool is64 = (g_is64 != 0);
    int src = load_idx(edges, e, is64);
    int dst = load_idx(edges, (long long)E + e, is64);
    int p = atomicAdd(&g_ofs[dst], 1);
    g_ssrc[p] = src;
    g_sdst[p] = dst;
    g_sw[p]   = ((const float2*)ea)[e];
}

// ---------------------------------------------------------------------------
// Per-node precompute into PADDED rows:
//   A[n,k] = relu?(x[n])·Wm1[0:C,k] + bm1[k]   (k<200; zero for k>=200)
//   B[n,k] = relu?(x[n])·Wm1[C:2C,k]           (k<200; zero for k>=200)
// ---------------------------------------------------------------------------
template <int C_IN, bool RELU_IN>
__global__ void precomp_ab_kernel(const float* __restrict__ x,
                                  const float* __restrict__ Wm1,
                                  const float* __restrict__ bm1,
                                  float* __restrict__ A,
                                  float* __restrict__ B,
                                  int N) {
    int idx = blockIdx.x * blockDim.x + threadIdx.x;
    if (idx >= N * NMSGP) return;
    int n = idx / NMSGP;
    int k = idx - n * NMSGP;
    if (k >= NMSG) { A[idx] = 0.f; B[idx] = 0.f; return; }
    float a = bm1[k];
    float b = 0.f;
#pragma unroll
    for (int c = 0; c < C_IN; c++) {
        float xv = x[(size_t)n * C_IN + c];
        if (RELU_IN) xv = fmaxf(xv, 0.f);
        a = fmaf(xv, Wm1[c * NMSG + k], a);
        b = fmaf(xv, Wm1[(C_IN + c) * NMSG + k], b);
    }
    A[idx] = a;
    B[idx] = b;
}

// ---------------------------------------------------------------------------
// Node self-term + aggregation buffer init
// ---------------------------------------------------------------------------
template <int C_IN, int C_OUT, bool RELU_IN>
__global__ void node_init_kernel(const float* __restrict__ x,
                                 const float* __restrict__ W1,
                                 const float* __restrict__ b1,
                                 float* __restrict__ out,
                                 int N) {
    int idx = blockIdx.x * blockDim.x + threadIdx.x;
    if (idx >= N * C_OUT) return;
    int n  = idx / C_OUT;
    int co = idx - n * C_OUT;
    float v = b1[co];
#pragma unroll
    for (int c = 0; c < C_IN; c++) {
        float xv = x[(size_t)n * C_IN + c];
        if (RELU_IN) xv = fmaxf(xv, 0.f);
        v = fmaf(xv, W1[c * C_OUT + co], v);
    }
    out[idx] = v;
}

// ---------------------------------------------------------------------------
// Edge kernel: thread-per-edge, B staged through shared in 128B-line chunks.
// ---------------------------------------------------------------------------
template <int C_IN, int C_OUT, bool RELU_IN>
__global__ void __launch_bounds__(EPB, 2)
edge_kernel(const int* __restrict__ srcArr,
            const int* __restrict__ dstArr,
            const float2* __restrict__ wArr,
            const float* __restrict__ x,
            const float* __restrict__ A,
            const float* __restrict__ B,
            const float* __restrict__ Wm1,
            const float* __restrict__ Wm2,
            const float* __restrict__ bm2,
            const float* __restrict__ W2,
            const float* __restrict__ b2,
            float* __restrict__ out,
            int E) {
    constexpr int C4  = (C_IN + 3) / 4;
    constexpr int CIP = C4 * 4;
    constexpr int CP2 = CIP / 2;
    constexpr int CO4 = (C_OUT + 3) / 4;
    constexpr int COP = CO4 * 4;

    extern __shared__ float sm[];
    float* sB   = sm;                        // EPB * 36
    float* sWE  = sB   + EPB * 36;           // 2 * 200
    float* sWm2 = sWE  + 2 * NMSG;           // 200 * CIP
    float* sW2  = sWm2 + NMSG * CIP;         // C_IN * COP
    float* sbm2 = sW2  + C_IN * COP;         // 32
    float* sb2  = sbm2 + 32;                 // 32
    int*   sSrc = (int*)(sb2 + 32);          // EPB
    int*   sDst = sSrc + EPB;                // EPB

    const int tid = threadIdx.x;
    for (int i = tid; i < 2 * NMSG; i += EPB) sWE[i] = Wm1[2 * C_IN * NMSG + i];
    for (int i = tid; i < NMSG * CIP; i += EPB) {
        int k = i / CIP, c = i - k * CIP;
        sWm2[i] = (c < C_IN) ? Wm2[k * C_IN + c] : 0.f;
    }
    for (int i = tid; i < C_IN * COP; i += EPB) {
        int c = i / COP, co = i - c * COP;
        sW2[i] = (co < C_OUT) ? W2[c * C_OUT + co] : 0.f;
    }
    for (int i = tid; i < 32; i += EPB) {
        sbm2[i] = (i < C_IN)  ? bm2[i] : 0.f;
        sb2[i]  = (i < C_OUT) ? b2[i]  : 0.f;
    }

    const int base  = blockIdx.x * EPB;
    const int nrows = min(EPB, E - base);
    const int e     = base + tid;
    const bool valid = (tid < nrows);

    sSrc[tid] = valid ? srcArr[e] : 0;
    sDst[tid] = valid ? dstArr[e] : 0;
    __syncthreads();

    const int src = sSrc[tid];
    const int dst = sDst[tid];
    float2 w = make_float2(0.f, 0.f);
    if (valid) w = wArr[e];

    const float4* A4  = (const float4*)(A + (size_t)dst * NMSGP);
    const float4* WE0 = (const float4*)(sWE);
    const float4* WE1 = (const float4*)(sWE + NMSG);
    float4* sB4 = (float4*)sB;

    u64 macc[CP2];
#pragma unroll
    for (int p = 0; p < CP2; p++) macc[p] = 0ull;

#pragma unroll 1
    for (int cc = 0; cc < 7; cc++) {
        // ---- coalesced load phase: whole 128B lines of B rows ----
#pragma unroll
        for (int i = 0; i < 8; i++) {
            int f4  = tid + EPB * i;          // 0 .. 4095
            int row = f4 >> 3;
            int col = f4 & 7;
            if (row < nrows) {
                const float4* bp = (const float4*)(B + (size_t)sSrc[row] * NMSGP);
                sB4[row * PADF4 + (col & 7)] = bp[cc * 8 + col];
            }
        }
        __syncthreads();

        if (valid) {
            const int kgmax = (cc == 6) ? 2 : 8;   // k >= 200 contributes 0
#pragma unroll
            for (int kg = 0; kg < 8; kg++) {
                if (kg >= kgmax) break;
                float4 bq = sB4[tid * PADF4 + kg];
                float4 aq = A4[cc * 8 + kg];
                float4 u0 = WE0[cc * 8 + kg];
                float4 u1 = WE1[cc * 8 + kg];
                float h0 = fmaxf(fmaf(w.x, u0.x, fmaf(w.y, u1.x, aq.x + bq.x)), 0.f);
                float h1 = fmaxf(fmaf(w.x, u0.y, fmaf(w.y, u1.y, aq.y + bq.y)), 0.f);
                float h2 = fmaxf(fmaf(w.x, u0.z, fmaf(w.y, u1.z, aq.z + bq.z)), 0.f);
                float h3 = fmaxf(fmaf(w.x, u0.w, fmaf(w.y, u1.w, aq.w + bq.w)), 0.f);
                u64 h02 = pack2(h0), h12 = pack2(h1), h22 = pack2(h2), h32 = pack2(h3);
                int k0 = cc * 32 + kg * 4;
                const u64* r0 = (const u64*)(sWm2 + (k0 + 0) * CIP);
                const u64* r1 = (const u64*)(sWm2 + (k0 + 1) * CIP);
                const u64* r2 = (const u64*)(sWm2 + (k0 + 2) * CIP);
                const u64* r3 = (const u64*)(sWm2 + (k0 + 3) * CIP);
#pragma unroll
                for (int p = 0; p < CP2; p++) {
                    u64 m = macc[p];
                    m = fma2(h02, r0[p], m);
                    m = fma2(h12, r1[p], m);
                    m = fma2(h22, r2[p], m);
                    m = fma2(h32, r3[p], m);
                    macc[p] = m;
                }
            }
        }
        __syncthreads();
    }

    if (!valid) return;

    // unpack m
    float m[CIP];
#pragma unroll
    for (int p = 0; p < CP2; p++) {
        float2 f = unpack2(macc[p]);
        m[2 * p]     = f.x;
        m[2 * p + 1] = f.y;
    }

    // msg = ((m + bm2) * (xi - xj)) @ W2 + b2
    float4 vacc[CO4];
    const float4* sb24 = (const float4*)sb2;
#pragma unroll
    for (int j = 0; j < CO4; j++) vacc[j] = sb24[j];

    const float* xd = x + (size_t)dst * C_IN;
    const float* xs = x + (size_t)src * C_IN;
#pragma unroll
    for (int c = 0; c < C_IN; c++) {
        float xi = xd[c], xj = xs[c];
        if (RELU_IN) { xi = fmaxf(xi, 0.f); xj = fmaxf(xj, 0.f); }
        float t = (m[c] + sbm2[c]) * (xi - xj);
        const float4* wr = (const float4*)(sW2 + c * COP);
#pragma unroll
        for (int j = 0; j < CO4; j++) {
            float4 q = wr[j];
            vacc[j].x = fmaf(t, q.x, vacc[j].x);
            vacc[j].y = fmaf(t, q.y, vacc[j].y);
            vacc[j].z = fmaf(t, q.z, vacc[j].z);
            vacc[j].w = fmaf(t, q.w, vacc[j].w);
        }
    }

    float* op = out + (size_t)dst * C_OUT;
#pragma unroll
    for (int j = 0; j < CO4; j++) {
        int co = 4 * j;
        if (co + 0 < C_OUT) atomicAdd(op + co + 0, vacc[j].x);
        if (co + 1 < C_OUT) atomicAdd(op + co + 1, vacc[j].y);
        if (co + 2 < C_OUT) atomicAdd(op + co + 2, vacc[j].z);
        if (co + 3 < C_OUT) atomicAdd(op + co + 3, vacc[j].w);
    }
}

// ---------------------------------------------------------------------------
// Host-side helpers
// ---------------------------------------------------------------------------
template <int C_IN, int C_OUT>
static constexpr size_t edge_smem_bytes() {
    constexpr int CIP = ((C_IN + 3) / 4) * 4;
    constexpr int COP = ((C_OUT + 3) / 4) * 4;
    size_t f = (size_t)EPB * 36 + 2 * NMSG + (size_t)NMSG * CIP + (size_t)C_IN * COP + 64;
    return (f + 2 * EPB) * 4;
}

template <int C_IN, int C_OUT, bool RELU_IN>
static void run_layer(const float* xin,
                      const float* const* W,   // W1,b1,Wm1,bm1,Wm2,bm2,W2,b2
                      const int* ssrc, const int* sdst, const float2* sw,
                      float* Abuf, float* Bbuf,
                      float* xout,
                      int N, int E) {
    precomp_ab_kernel<C_IN, RELU_IN><<<(N * NMSGP + 255) / 256, 256>>>(
        xin, W[2], W[3], Abuf, Bbuf, N);
    node_init_kernel<C_IN, C_OUT, RELU_IN><<<(N * C_OUT + 255) / 256, 256>>>(
        xin, W[0], W[1], xout, N);
    size_t smem = edge_smem_bytes<C_IN, C_OUT>();
    cudaFuncSetAttribute(edge_kernel<C_IN, C_OUT, RELU_IN>,
                         cudaFuncAttributeMaxDynamicSharedMemorySize, (int)smem);
    edge_kernel<C_IN, C_OUT, RELU_IN><<<(E + EPB - 1) / EPB, EPB, smem>>>(
        ssrc, sdst, sw, xin, Abuf, Bbuf, W[2], W[4], W[5], W[6], W[7], xout, E);
}

extern "C" void kernel_launch(void* const* d_in, const int* in_sizes, int n_in,
                              void* d_out, int out_size) {
    const float* feat  = (const float*)d_in[0];
    const void*  edges = d_in[1];
    const float* ew    = (const float*)d_in[2];

    const float* P[24];
    for (int i = 0; i < 24; i++) P[i] = (const float*)d_in[3 + i];
    // P[0..7] = layer d, P[8..15] = layer h, P[16..23] = layer o

    int N = in_sizes[0];        // NUM_IN == 1 -> element count == node count
    int E = in_sizes[2] / 2;    // weights is [E,2]

    float *x0, *x1, *A, *B;
    int *ssrc, *sdst;
    float2 *sw;
    cudaGetSymbolAddress((void**)&x0,   g_x0);
    cudaGetSymbolAddress((void**)&x1,   g_x1);
    cudaGetSymbolAddress((void**)&A,    g_A);
    cudaGetSymbolAddress((void**)&B,    g_B);
    cudaGetSymbolAddress((void**)&ssrc, g_ssrc);
    cudaGetSymbolAddress((void**)&sdst, g_sdst);
    cudaGetSymbolAddress((void**)&sw,   g_sw);

    // Preprocessing: dtype detect + counting sort by dst (parallel scan)
    int nb = (N + 1023) / 1024;
    detect_edges_kernel<<<1, 32>>>((const long long*)edges);
    zero_hist_kernel<<<(N + 255) / 256, 256>>>(N);
    hist_kernel<<<(E + 255) / 256, 256>>>(edges, E);
    scan1_kernel<<<nb, 1024>>>(N);
    scan2_kernel<<<1, 32>>>(nb);
    scan3_kernel<<<nb, 1024>>>(N);
    scatter_kernel<<<(E + 255) / 256, 256>>>(edges, ew, E);

    run_layer<1, 30, false>(feat, P + 0,  ssrc, sdst, sw, A, B, x0, N, E);
    run_layer<30, 30, true>(x0,  P + 8,  ssrc, sdst, sw, A, B, x1, N, E);
    run_layer<30, 30, true>(x1,  P + 8,  ssrc, sdst, sw, A, B, x0, N, E);
    run_layer<30, 30, true>(x0,  P + 8,  ssrc, sdst, sw, A, B, x1, N, E);
    run_layer<30, 1, true>(x1,   P + 16, ssrc, sdst, sw, A, B, (float*)d_out, N, E);
}

// round 5
// speedup vs baseline: 1.4080x; 1.4080x over previous
#include <cuda_runtime.h>
#include <cstdint>

#define NN      50000
#define NE      800000
#define NMSG    200

// ---------------------------------------------------------------------------
// Static device scratch
// ---------------------------------------------------------------------------
__device__ __align__(16) float g_x0[NN * 30];
__device__ __align__(16) float g_x1[NN * 30];
__device__ __align__(16) float g_A [NN * NMSG];
__device__ __align__(16) float g_B [NN * NMSG];
__device__ int g_is64;
__device__ int g_cnt[NN];
__device__ int g_ofs[NN];
__device__ int g_bsum[64];
__device__ int g_ssrc[NE];
__device__ int g_sdst[NE];
__device__ __align__(8) float2 g_sw[NE];

// ---------------------------------------------------------------------------
// Packed f32x2 helpers
// ---------------------------------------------------------------------------
typedef unsigned long long u64;
__device__ __forceinline__ u64 fma2(u64 a, u64 b, u64 c) {
    u64 d; asm("fma.rn.f32x2 %0, %1, %2, %3;" : "=l"(d) : "l"(a), "l"(b), "l"(c)); return d;
}
__device__ __forceinline__ u64 pack2(float x) {
    u64 d; asm("mov.b64 %0, {%1, %1};" : "=l"(d) : "f"(x)); return d;
}
__device__ __forceinline__ u64 pairf(float lo, float hi) {
    u64 d; asm("mov.b64 %0, {%1, %2};" : "=l"(d) : "f"(lo), "f"(hi)); return d;
}
__device__ __forceinline__ float2 unpack2(u64 a) {
    float2 f; asm("mov.b64 {%0, %1}, %2;" : "=f"(f.x), "=f"(f.y) : "l"(a)); return f;
}

// ---------------------------------------------------------------------------
// Edge dtype detection (int64 per reference vs int32 if JAX x64 disabled)
// ---------------------------------------------------------------------------
__global__ void detect_edges_kernel(const long long* __restrict__ e64) {
    if (threadIdx.x == 0 && blockIdx.x == 0) {
        int ok = 1;
        for (int i = 0; i < 16; i++) {
            long long v = e64[i];
            if (v < 0 || v >= NN) ok = 0;
        }
        g_is64 = ok;
    }
}
__device__ __forceinline__ int load_idx(const void* edges, long long pos, bool is64) {
    if (is64) return (int)((const long long*)edges)[pos];
    return ((const int*)edges)[pos];
}

// ---------------------------------------------------------------------------
// Counting sort by dst (parallel scan)
// ---------------------------------------------------------------------------
__global__ void zero_hist_kernel(int N) {
    int i = blockIdx.x * blockDim.x + threadIdx.x;
    if (i < N) g_cnt[i] = 0;
}
__global__ void hist_kernel(const void* __restrict__ edges, int E) {
    int e = blockIdx.x * blockDim.x + threadIdx.x;
    if (e >= E) return;
    bool is64 = (g_is64 != 0);
    atomicAdd(&g_cnt[load_idx(edges, (long long)E + e, is64)], 1);
}
__global__ void scan1_kernel(int N) {
    __shared__ int s[1024];
    int i = blockIdx.x * 1024 + threadIdx.x;
    int v = (i < N) ? g_cnt[i] : 0;
    s[threadIdx.x] = v;
    __syncthreads();
    for (int off = 1; off < 1024; off <<= 1) {
        int t = (threadIdx.x >= (unsigned)off) ? s[threadIdx.x - off] : 0;
        __syncthreads();
        s[threadIdx.x] += t;
        __syncthreads();
    }
    if (i < N) g_ofs[i] = s[threadIdx.x] - v;
    if (threadIdx.x == 1023) g_bsum[blockIdx.x] = s[1023];
}
__global__ void scan2_kernel(int nb) {
    if (threadIdx.x == 0 && blockIdx.x == 0) {
        int acc = 0;
        for (int b = 0; b < nb; b++) { int t = g_bsum[b]; g_bsum[b] = acc; acc += t; }
    }
}
__global__ void scan3_kernel(int N) {
    int i = blockIdx.x * 1024 + threadIdx.x;
    if (i < N) g_ofs[i] += g_bsum[blockIdx.x];
}
__global__ void scatter_kernel(const void* __restrict__ edges,
                               const float* __restrict__ ea, int E) {
    int e = blockIdx.x * blockDim.x + threadIdx.x;
    if (e >= E) return;
    bool is64 = (g_is64 != 0);
    int src = load_idx(edges, e, is64);
    int dst = load_idx(edges, (long long)E + e, is64);
    int p = atomicAdd(&g_ofs[dst], 1);
    g_ssrc[p] = src;
    g_sdst[p] = dst;
    g_sw[p]   = ((const float2*)ea)[e];
}

// ---------------------------------------------------------------------------
// Per-node precompute (hidden/output layers, C_IN=30):
//   A[n,k] = relu(x[n])·Wm1[0:C,k] + bm1[k],  B[n,k] = relu(x[n])·Wm1[C:2C,k]
// ---------------------------------------------------------------------------
template <int C_IN, bool RELU_IN>
__global__ void precomp_ab_kernel(const float* __restrict__ x,
                                  const float* __restrict__ Wm1,
                                  const float* __restrict__ bm1,
                                  float* __restrict__ A,
                                  float* __restrict__ B,
                                  int N) {
    int idx = blockIdx.x * blockDim.x + threadIdx.x;
    if (idx >= N * NMSG) return;
    int n = idx / NMSG;
    int k = idx - n * NMSG;
    float a = bm1[k];
    float b = 0.f;
#pragma unroll
    for (int c = 0; c < C_IN; c++) {
        float xv = x[(size_t)n * C_IN + c];
        if (RELU_IN) xv = fmaxf(xv, 0.f);
        a = fmaf(xv, Wm1[c * NMSG + k], a);
        b = fmaf(xv, Wm1[(C_IN + c) * NMSG + k], b);
    }
    A[idx] = a;
    B[idx] = b;
}

// ---------------------------------------------------------------------------
// Node self-term + aggregation buffer init
// ---------------------------------------------------------------------------
template <int C_IN, int C_OUT, bool RELU_IN>
__global__ void node_init_kernel(const float* __restrict__ x,
                                 const float* __restrict__ W1,
                                 const float* __restrict__ b1,
                                 float* __restrict__ out,
                                 int N) {
    int idx = blockIdx.x * blockDim.x + threadIdx.x;
    if (idx >= N * C_OUT) return;
    int n  = idx / C_OUT;
    int co = idx - n * C_OUT;
    float v = b1[co];
#pragma unroll
    for (int c = 0; c < C_IN; c++) {
        float xv = x[(size_t)n * C_IN + c];
        if (RELU_IN) xv = fmaxf(xv, 0.f);
        v = fmaf(xv, W1[c * C_OUT + co], v);
    }
    out[idx] = v;
}

// ---------------------------------------------------------------------------
// Specialized d-layer edge kernel (C_IN=1): h built from scalar x, no A/B.
//   Wm1 rows for C_IN=1: [0]=xi coeff, [1]=xj coeff, [2]=w0, [3]=w1
//   m = sum_k relu(bm1_k + xi*W0_k + xj*W1_k + w·WE_k) * Wm2_k
//   t = (m + bm2) * (xi - xj);  msg_co = t*W2_co + b2_co -> atomic
// ---------------------------------------------------------------------------
template <int C_OUT>
__global__ void __launch_bounds__(256)
edge_d_kernel(const int* __restrict__ srcArr,
              const int* __restrict__ dstArr,
              const float2* __restrict__ wArr,
              const float* __restrict__ x,
              const float* __restrict__ Wm1,
              const float* __restrict__ bm1,
              const float* __restrict__ Wm2,
              const float* __restrict__ bm2,
              const float* __restrict__ W2,
              const float* __restrict__ b2,
              float* __restrict__ out,
              int E) {
    __shared__ __align__(16) float sW0[NMSG], sW1[NMSG], sE0[NMSG], sE1[NMSG];
    __shared__ __align__(16) float sB1[NMSG], sM2[NMSG];
    __shared__ float sW2[32], sb2[32], sbm2s;

    const int tid = threadIdx.x;
    for (int i = tid; i < NMSG; i += 256) {
        sW0[i] = Wm1[0 * NMSG + i];
        sW1[i] = Wm1[1 * NMSG + i];
        sE0[i] = Wm1[2 * NMSG + i];
        sE1[i] = Wm1[3 * NMSG + i];
        sB1[i] = bm1[i];
        sM2[i] = Wm2[i];
    }
    for (int i = tid; i < 32; i += 256) {
        sW2[i] = (i < C_OUT) ? W2[i] : 0.f;
        sb2[i] = (i < C_OUT) ? b2[i] : 0.f;
    }
    if (tid == 0) sbm2s = bm2[0];
    __syncthreads();

    int e = blockIdx.x * 256 + tid;
    if (e >= E) return;

    const int src = srcArr[e];
    const int dst = dstArr[e];
    const float2 w = wArr[e];
    const float xi = x[dst];
    const float xj = x[src];

    float m = 0.f;
#pragma unroll 2
    for (int g = 0; g < NMSG / 4; g++) {
        float4 w0 = ((const float4*)sW0)[g];
        float4 w1 = ((const float4*)sW1)[g];
        float4 e0 = ((const float4*)sE0)[g];
        float4 e1 = ((const float4*)sE1)[g];
        float4 bb = ((const float4*)sB1)[g];
        float4 m2 = ((const float4*)sM2)[g];
        float h0 = fmaxf(fmaf(xi, w0.x, fmaf(xj, w1.x, fmaf(w.x, e0.x, fmaf(w.y, e1.x, bb.x)))), 0.f);
        float h1 = fmaxf(fmaf(xi, w0.y, fmaf(xj, w1.y, fmaf(w.x, e0.y, fmaf(w.y, e1.y, bb.y)))), 0.f);
        float h2 = fmaxf(fmaf(xi, w0.z, fmaf(xj, w1.z, fmaf(w.x, e0.z, fmaf(w.y, e1.z, bb.z)))), 0.f);
        float h3 = fmaxf(fmaf(xi, w0.w, fmaf(xj, w1.w, fmaf(w.x, e0.w, fmaf(w.y, e1.w, bb.w)))), 0.f);
        m = fmaf(h0, m2.x, fmaf(h1, m2.y, fmaf(h2, m2.z, fmaf(h3, m2.w, m))));
    }

    float t = (m + sbm2s) * (xi - xj);
    float* op = out + (size_t)dst * C_OUT;
#pragma unroll
    for (int co = 0; co < C_OUT; co++)
        atomicAdd(op + co, fmaf(t, sW2[co], sb2[co]));
}

// ---------------------------------------------------------------------------
// General edge kernel (C_IN=30): thread-per-edge, f32x2 math
// ---------------------------------------------------------------------------
template <int C_IN, int C_OUT, bool RELU_IN>
__global__ void __launch_bounds__(256)
edge_kernel(const int* __restrict__ srcArr,
            const int* __restrict__ dstArr,
            const float2* __restrict__ wArr,
            const float* __restrict__ x,
            const float* __restrict__ A,
            const float* __restrict__ B,
            const float* __restrict__ Wm1,
            const float* __restrict__ Wm2,
            const float* __restrict__ bm2,
            const float* __restrict__ W2,
            const float* __restrict__ b2,
            float* __restrict__ out,
            int E) {
    constexpr int C4  = (C_IN + 3) / 4;
    constexpr int CIP = C4 * 4;
    constexpr int CP2 = CIP / 2;
    constexpr int CO4 = (C_OUT + 3) / 4;
    constexpr int COP = CO4 * 4;
    constexpr int OP2 = COP / 2;

    __shared__ __align__(16) float sWE[2 * NMSG];
    __shared__ __align__(16) float sWm2[NMSG * CIP];
    __shared__ __align__(16) float sW2[C_IN * COP];
    __shared__ float sbm2[32];
    __shared__ float sb2[32];

    const int tid = threadIdx.x;
    for (int i = tid; i < 2 * NMSG; i += 256) sWE[i] = Wm1[2 * C_IN * NMSG + i];
    for (int i = tid; i < NMSG * CIP; i += 256) {
        int k = i / CIP, c = i - k * CIP;
        sWm2[i] = (c < C_IN) ? Wm2[k * C_IN + c] : 0.f;
    }
    for (int i = tid; i < C_IN * COP; i += 256) {
        int c = i / COP, co = i - c * COP;
        sW2[i] = (co < C_OUT) ? W2[c * C_OUT + co] : 0.f;
    }
    for (int i = tid; i < 32; i += 256) {
        sbm2[i] = (i < C_IN)  ? bm2[i] : 0.f;
        sb2[i]  = (i < C_OUT) ? b2[i]  : 0.f;
    }
    __syncthreads();

    int e = blockIdx.x * 256 + tid;
    if (e >= E) return;

    const int src = srcArr[e];
    const int dst = dstArr[e];
    const float2 w = wArr[e];

    const float4* A4  = (const float4*)(A + (size_t)dst * NMSG);
    const float4* B4  = (const float4*)(B + (size_t)src * NMSG);
    const float4* WE0 = (const float4*)(sWE);
    const float4* WE1 = (const float4*)(sWE + NMSG);

    u64 macc[CP2];
#pragma unroll
    for (int p = 0; p < CP2; p++) macc[p] = 0ull;

#pragma unroll 2
    for (int kg = 0; kg < NMSG / 4; kg++) {
        float4 a = A4[kg];
        float4 b = B4[kg];
        float4 u0 = WE0[kg];
        float4 u1 = WE1[kg];
        float h0 = fmaxf(fmaf(w.x, u0.x, fmaf(w.y, u1.x, a.x + b.x)), 0.f);
        float h1 = fmaxf(fmaf(w.x, u0.y, fmaf(w.y, u1.y, a.y + b.y)), 0.f);
        float h2 = fmaxf(fmaf(w.x, u0.z, fmaf(w.y, u1.z, a.z + b.z)), 0.f);
        float h3 = fmaxf(fmaf(w.x, u0.w, fmaf(w.y, u1.w, a.w + b.w)), 0.f);
        u64 h02 = pack2(h0), h12 = pack2(h1), h22 = pack2(h2), h32 = pack2(h3);

        const float4* r0 = (const float4*)(sWm2 + (4 * kg + 0) * CIP);
        const float4* r1 = (const float4*)(sWm2 + (4 * kg + 1) * CIP);
        const float4* r2 = (const float4*)(sWm2 + (4 * kg + 2) * CIP);
        const float4* r3 = (const float4*)(sWm2 + (4 * kg + 3) * CIP);
#pragma unroll
        for (int j = 0; j < C4; j++) {
            float4 q0 = r0[j], q1 = r1[j], q2 = r2[j], q3 = r3[j];
            u64 lo = macc[2 * j], hi = macc[2 * j + 1];
            lo = fma2(h02, pairf(q0.x, q0.y), lo);
            hi = fma2(h02, pairf(q0.z, q0.w), hi);
            lo = fma2(h12, pairf(q1.x, q1.y), lo);
            hi = fma2(h12, pairf(q1.z, q1.w), hi);
            lo = fma2(h22, pairf(q2.x, q2.y), lo);
            hi = fma2(h22, pairf(q2.z, q2.w), hi);
            lo = fma2(h32, pairf(q3.x, q3.y), lo);
            hi = fma2(h32, pairf(q3.z, q3.w), hi);
            macc[2 * j] = lo;
            macc[2 * j + 1] = hi;
        }
    }

    // unpack m
    float m[CIP];
#pragma unroll
    for (int p = 0; p < CP2; p++) {
        float2 f = unpack2(macc[p]);
        m[2 * p]     = f.x;
        m[2 * p + 1] = f.y;
    }

    // msg = ((m + bm2) * (xi - xj)) @ W2 + b2
    u64 vacc[OP2];
#pragma unroll
    for (int p = 0; p < OP2; p++) vacc[p] = pairf(sb2[2 * p], sb2[2 * p + 1]);

    const float* xd = x + (size_t)dst * C_IN;
    const float* xs = x + (size_t)src * C_IN;
#pragma unroll
    for (int c = 0; c < C_IN; c++) {
        float xi = xd[c], xj = xs[c];
        if (RELU_IN) { xi = fmaxf(xi, 0.f); xj = fmaxf(xj, 0.f); }
        float t = (m[c] + sbm2[c]) * (xi - xj);
        u64 t2 = pack2(t);
        const float4* wr = (const float4*)(sW2 + c * COP);
#pragma unroll
        for (int j = 0; j < CO4; j++) {
            float4 q = wr[j];
            vacc[2 * j]     = fma2(t2, pairf(q.x, q.y), vacc[2 * j]);
            vacc[2 * j + 1] = fma2(t2, pairf(q.z, q.w), vacc[2 * j + 1]);
        }
    }

    float* op = out + (size_t)dst * C_OUT;
#pragma unroll
    for (int p = 0; p < OP2; p++) {
        float2 v = unpack2(vacc[p]);
        int co = 2 * p;
        if (co + 0 < C_OUT) atomicAdd(op + co + 0, v.x);
        if (co + 1 < C_OUT) atomicAdd(op + co + 1, v.y);
    }
}

// ---------------------------------------------------------------------------
// Host-side layer driver (hidden/output layers)
// ---------------------------------------------------------------------------
template <int C_IN, int C_OUT, bool RELU_IN>
static void run_layer(const float* xin,
                      const float* const* W,   // W1,b1,Wm1,bm1,Wm2,bm2,W2,b2
                      const int* ssrc, const int* sdst, const float2* sw,
                      float* Abuf, float* Bbuf,
                      float* xout,
                      int N, int E) {
    precomp_ab_kernel<C_IN, RELU_IN><<<(N * NMSG + 255) / 256, 256>>>(
        xin, W[2], W[3], Abuf, Bbuf, N);
    node_init_kernel<C_IN, C_OUT, RELU_IN><<<(N * C_OUT + 255) / 256, 256>>>(
        xin, W[0], W[1], xout, N);
    edge_kernel<C_IN, C_OUT, RELU_IN><<<(E + 255) / 256, 256>>>(
        ssrc, sdst, sw, xin, Abuf, Bbuf, W[2], W[4], W[5], W[6], W[7], xout, E);
}

extern "C" void kernel_launch(void* const* d_in, const int* in_sizes, int n_in,
                              void* d_out, int out_size) {
    const float* feat  = (const float*)d_in[0];
    const void*  edges = d_in[1];
    const float* ew    = (const float*)d_in[2];

    const float* P[24];
    for (int i = 0; i < 24; i++) P[i] = (const float*)d_in[3 + i];
    // P[0..7] = layer d, P[8..15] = layer h, P[16..23] = layer o

    int N = in_sizes[0];        // NUM_IN == 1 -> element count == node count
    int E = in_sizes[2] / 2;    // weights is [E,2]

    float *x0, *x1, *A, *B;
    int *ssrc, *sdst;
    float2 *sw;
    cudaGetSymbolAddress((void**)&x0,   g_x0);
    cudaGetSymbolAddress((void**)&x1,   g_x1);
    cudaGetSymbolAddress((void**)&A,    g_A);
    cudaGetSymbolAddress((void**)&B,    g_B);
    cudaGetSymbolAddress((void**)&ssrc, g_ssrc);
    cudaGetSymbolAddress((void**)&sdst, g_sdst);
    cudaGetSymbolAddress((void**)&sw,   g_sw);

    // Preprocessing: dtype detect + counting sort by dst (parallel scan)
    int nb = (N + 1023) / 1024;
    detect_edges_kernel<<<1, 32>>>((const long long*)edges);
    zero_hist_kernel<<<(N + 255) / 256, 256>>>(N);
    hist_kernel<<<(E + 255) / 256, 256>>>(edges, E);
    scan1_kernel<<<nb, 1024>>>(N);
    scan2_kernel<<<1, 32>>>(nb);
    scan3_kernel<<<nb, 1024>>>(N);
    scatter_kernel<<<(E + 255) / 256, 256>>>(edges, ew, E);

    // d layer: specialized scalar-x edge kernel, no precomp needed.
    node_init_kernel<1, 30, false><<<(N * 30 + 255) / 256, 256>>>(
        feat, P[0], P[1], x0, N);
    edge_d_kernel<30><<<(E + 255) / 256, 256>>>(
        ssrc, sdst, sw, feat, P[2], P[3], P[4], P[5], P[6], P[7], x0, E);

    // hidden layers (shared weights) + output layer
    run_layer<30, 30, true>(x0,  P + 8,  ssrc, sdst, sw, A, B, x1, N, E);
    run_layer<30, 30, true>(x1,  P + 8,  ssrc, sdst, sw, A, B, x0, N, E);
    run_layer<30, 30, true>(x0,  P + 8,  ssrc, sdst, sw, A, B, x1, N, E);
    run_layer<30, 1, true>(x1,   P + 16, ssrc, sdst, sw, A, B, (float*)d_out, N, E);
}

// round 6
// speedup vs baseline: 1.7260x; 1.2258x over previous
#include <cuda_runtime.h>
#include <cstdint>

#define NN      50000
#define NE      800000
#define NMSG    200
#define TSTR    32            // Tagg row stride (floats)

// ---------------------------------------------------------------------------
// Static device scratch
// ---------------------------------------------------------------------------
__device__ __align__(16) float g_x0[NN * 30];
__device__ __align__(16) float g_x1[NN * 30];
__device__ __align__(16) float g_A [NN * NMSG];
__device__ __align__(16) float g_B [NN * NMSG];
__device__ __align__(16) float g_T [NN * TSTR];
__device__ int g_is64;
__device__ int g_cnt[NN];
__device__ int g_ofs[NN];
__device__ int g_bsum[64];
__device__ int g_ssrc[NE];
__device__ int g_sdst[NE];
__device__ __align__(8) float2 g_sw[NE];

// ---------------------------------------------------------------------------
// Packed f32x2 helpers
// ---------------------------------------------------------------------------
typedef unsigned long long u64;
__device__ __forceinline__ u64 fma2(u64 a, u64 b, u64 c) {
    u64 d; asm("fma.rn.f32x2 %0, %1, %2, %3;" : "=l"(d) : "l"(a), "l"(b), "l"(c)); return d;
}
__device__ __forceinline__ u64 pack2(float x) {
    u64 d; asm("mov.b64 %0, {%1, %1};" : "=l"(d) : "f"(x)); return d;
}
__device__ __forceinline__ u64 pairf(float lo, float hi) {
    u64 d; asm("mov.b64 %0, {%1, %2};" : "=l"(d) : "f"(lo), "f"(hi)); return d;
}
__device__ __forceinline__ float2 unpack2(u64 a) {
    float2 f; asm("mov.b64 {%0, %1}, %2;" : "=f"(f.x), "=f"(f.y) : "l"(a)); return f;
}

// ---------------------------------------------------------------------------
// Edge dtype detection
// ---------------------------------------------------------------------------
__global__ void detect_edges_kernel(const long long* __restrict__ e64) {
    if (threadIdx.x == 0 && blockIdx.x == 0) {
        int ok = 1;
        for (int i = 0; i < 16; i++) {
            long long v = e64[i];
            if (v < 0 || v >= NN) ok = 0;
        }
        g_is64 = ok;
    }
}
__device__ __forceinline__ int load_idx(const void* edges, long long pos, bool is64) {
    if (is64) return (int)((const long long*)edges)[pos];
    return ((const int*)edges)[pos];
}

// ---------------------------------------------------------------------------
// Counting sort by dst (parallel scan)
// ---------------------------------------------------------------------------
__global__ void zero_hist_kernel(int N) {
    int i = blockIdx.x * blockDim.x + threadIdx.x;
    if (i < N) g_cnt[i] = 0;
}
__global__ void hist_kernel(const void* __restrict__ edges, int E) {
    int e = blockIdx.x * blockDim.x + threadIdx.x;
    if (e >= E) return;
    bool is64 = (g_is64 != 0);
    atomicAdd(&g_cnt[load_idx(edges, (long long)E + e, is64)], 1);
}
__global__ void scan1_kernel(int N) {
    __shared__ int s[1024];
    int i = blockIdx.x * 1024 + threadIdx.x;
    int v = (i < N) ? g_cnt[i] : 0;
    s[threadIdx.x] = v;
    __syncthreads();
    for (int off = 1; off < 1024; off <<= 1) {
        int t = (threadIdx.x >= (unsigned)off) ? s[threadIdx.x - off] : 0;
        __syncthreads();
        s[threadIdx.x] += t;
        __syncthreads();
    }
    if (i < N) g_ofs[i] = s[threadIdx.x] - v;
    if (threadIdx.x == 1023) g_bsum[blockIdx.x] = s[1023];
}
__global__ void scan2_kernel(int nb) {
    if (threadIdx.x == 0 && blockIdx.x == 0) {
        int acc = 0;
        for (int b = 0; b < nb; b++) { int t = g_bsum[b]; g_bsum[b] = acc; acc += t; }
    }
}
__global__ void scan3_kernel(int N) {
    int i = blockIdx.x * 1024 + threadIdx.x;
    if (i < N) g_ofs[i] += g_bsum[blockIdx.x];
}
__global__ void scatter_kernel(const void* __restrict__ edges,
                               const float* __restrict__ ea, int E) {
    int e = blockIdx.x * blockDim.x + threadIdx.x;
    if (e >= E) return;
    bool is64 = (g_is64 != 0);
    int src = load_idx(edges, e, is64);
    int dst = load_idx(edges, (long long)E + e, is64);
    int p = atomicAdd(&g_ofs[dst], 1);
    g_ssrc[p] = src;
    g_sdst[p] = dst;
    g_sw[p]   = ((const float2*)ea)[e];
}

// ---------------------------------------------------------------------------
// Zero the t-aggregation buffer
// ---------------------------------------------------------------------------
__global__ void zeroT_kernel(float* __restrict__ T, int n) {
    int i = blockIdx.x * blockDim.x + threadIdx.x;
    if (i < n) T[i] = 0.f;
}

// ---------------------------------------------------------------------------
// Per-node precompute (C_IN=30)
// ---------------------------------------------------------------------------
template <int C_IN, bool RELU_IN>
__global__ void precomp_ab_kernel(const float* __restrict__ x,
                                  const float* __restrict__ Wm1,
                                  const float* __restrict__ bm1,
                                  float* __restrict__ A,
                                  float* __restrict__ B,
                                  int N) {
    int idx = blockIdx.x * blockDim.x + threadIdx.x;
    if (idx >= N * NMSG) return;
    int n = idx / NMSG;
    int k = idx - n * NMSG;
    float a = bm1[k];
    float b = 0.f;
#pragma unroll
    for (int c = 0; c < C_IN; c++) {
        float xv = x[(size_t)n * C_IN + c];
        if (RELU_IN) xv = fmaxf(xv, 0.f);
        a = fmaf(xv, Wm1[c * NMSG + k], a);
        b = fmaf(xv, Wm1[(C_IN + c) * NMSG + k], b);
    }
    A[idx] = a;
    B[idx] = b;
}

// ---------------------------------------------------------------------------
// Node finish: out[n,co] = b1 + deg*b2 + x@W1 + Tagg@W2
// ---------------------------------------------------------------------------
template <int C_IN, int C_OUT, bool RELU_IN>
__global__ void node_finish_kernel(const float* __restrict__ x,
                                   const float* __restrict__ W1,
                                   const float* __restrict__ b1,
                                   const float* __restrict__ W2,
                                   const float* __restrict__ b2,
                                   const float* __restrict__ Tagg,
                                   const int* __restrict__ cnt,
                                   float* __restrict__ out,
                                   int N) {
    int idx = blockIdx.x * blockDim.x + threadIdx.x;
    if (idx >= N * C_OUT) return;
    int n  = idx / C_OUT;
    int co = idx - n * C_OUT;
    float v = b1[co] + (float)cnt[n] * b2[co];
#pragma unroll
    for (int c = 0; c < C_IN; c++) {
        float xv = x[(size_t)n * C_IN + c];
        if (RELU_IN) xv = fmaxf(xv, 0.f);
        v = fmaf(xv, W1[c * C_OUT + co], v);
        v = fmaf(Tagg[(size_t)n * TSTR + c], W2[c * C_OUT + co], v);
    }
    out[idx] = v;
}

// ---------------------------------------------------------------------------
// d-layer edge kernel (C_IN=1): scalar t, segmented-scan aggregation
// ---------------------------------------------------------------------------
__global__ void __launch_bounds__(256)
edge_d_kernel(const int* __restrict__ srcArr,
              const int* __restrict__ dstArr,
              const float2* __restrict__ wArr,
              const float* __restrict__ x,
              const float* __restrict__ Wm1,
              const float* __restrict__ bm1,
              const float* __restrict__ Wm2,
              const float* __restrict__ bm2,
              float* __restrict__ Tagg,
              int E) {
    __shared__ __align__(16) float sW0[NMSG], sW1[NMSG], sE0[NMSG], sE1[NMSG];
    __shared__ __align__(16) float sB1[NMSG], sM2[NMSG];
    __shared__ float sbm2s;

    const int tid = threadIdx.x;
    for (int i = tid; i < NMSG; i += 256) {
        sW0[i] = Wm1[0 * NMSG + i];
        sW1[i] = Wm1[1 * NMSG + i];
        sE0[i] = Wm1[2 * NMSG + i];
        sE1[i] = Wm1[3 * NMSG + i];
        sB1[i] = bm1[i];
        sM2[i] = Wm2[i];
    }
    if (tid == 0) sbm2s = bm2[0];
    __syncthreads();

    const int e = blockIdx.x * 256 + tid;
    const bool valid = (e < E);
    const int lane = tid & 31;

    int src = 0, dstL = 0, key = -1;
    float2 w = make_float2(0.f, 0.f);
    if (valid) {
        src  = srcArr[e];
        dstL = dstArr[e];
        key  = dstL;
        w    = wArr[e];
    }
    const float xi = x[dstL];
    const float xj = x[src];

    float m = 0.f;
#pragma unroll 2
    for (int g = 0; g < NMSG / 4; g++) {
        float4 w0 = ((const float4*)sW0)[g];
        float4 w1 = ((const float4*)sW1)[g];
        float4 e0 = ((const float4*)sE0)[g];
        float4 e1 = ((const float4*)sE1)[g];
        float4 bb = ((const float4*)sB1)[g];
        float4 m2 = ((const float4*)sM2)[g];
        float h0 = fmaxf(fmaf(xi, w0.x, fmaf(xj, w1.x, fmaf(w.x, e0.x, fmaf(w.y, e1.x, bb.x)))), 0.f);
        float h1 = fmaxf(fmaf(xi, w0.y, fmaf(xj, w1.y, fmaf(w.x, e0.y, fmaf(w.y, e1.y, bb.y)))), 0.f);
        float h2 = fmaxf(fmaf(xi, w0.z, fmaf(xj, w1.z, fmaf(w.x, e0.z, fmaf(w.y, e1.z, bb.z)))), 0.f);
        float h3 = fmaxf(fmaf(xi, w0.w, fmaf(xj, w1.w, fmaf(w.x, e0.w, fmaf(w.y, e1.w, bb.w)))), 0.f);
        m = fmaf(h0, m2.x, fmaf(h1, m2.y, fmaf(h2, m2.z, fmaf(h3, m2.w, m))));
    }

    float t = valid ? (m + sbm2s) * (xi - xj) : 0.f;

    // warp-segmented inclusive scan by key
#pragma unroll
    for (int r = 0; r < 5; r++) {
        int off = 1 << r;
        int ku = __shfl_up_sync(0xffffffffu, key, off);
        float tu = __shfl_up_sync(0xffffffffu, t, off);
        if (lane >= off && ku == key) t += tu;
    }
    int kn = __shfl_down_sync(0xffffffffu, key, 1);
    bool tail = (lane == 31) || (kn != key);
    if (valid && tail) atomicAdd(Tagg + (size_t)dstL * TSTR, t);
}

// ---------------------------------------------------------------------------
// Hidden/output edge kernel (C_IN=30): f32x2 GEMV, t-aggregation with
// warp-segmented reduction (edges are dst-sorted).
// ---------------------------------------------------------------------------
template <int C_IN, bool RELU_IN>
__global__ void __launch_bounds__(256)
edge_kernel(const int* __restrict__ srcArr,
            const int* __restrict__ dstArr,
            const float2* __restrict__ wArr,
            const float* __restrict__ x,
            const float* __restrict__ A,
            const float* __restrict__ B,
            const float* __restrict__ Wm1,
            const float* __restrict__ Wm2,
            const float* __restrict__ bm2,
            float* __restrict__ Tagg,
            int E) {
    constexpr int C4  = (C_IN + 3) / 4;
    constexpr int CIP = C4 * 4;
    constexpr int CP2 = CIP / 2;

    __shared__ __align__(16) float sWE[2 * NMSG];
    __shared__ __align__(16) float sWm2[NMSG * CIP];
    __shared__ float sbm2[CIP];

    const int tid = threadIdx.x;
    for (int i = tid; i < 2 * NMSG; i += 256) sWE[i] = Wm1[2 * C_IN * NMSG + i];
    for (int i = tid; i < NMSG * CIP; i += 256) {
        int k = i / CIP, c = i - k * CIP;
        sWm2[i] = (c < C_IN) ? Wm2[k * C_IN + c] : 0.f;
    }
    for (int i = tid; i < CIP; i += 256) sbm2[i] = (i < C_IN) ? bm2[i] : 0.f;
    __syncthreads();

    const int e = blockIdx.x * 256 + tid;
    const bool valid = (e < E);
    const int lane = tid & 31;

    int src = 0, dstL = 0, key = -1;
    float2 w = make_float2(0.f, 0.f);
    if (valid) {
        src  = srcArr[e];
        dstL = dstArr[e];
        key  = dstL;
        w    = wArr[e];
    }

    const float4* A4  = (const float4*)(A + (size_t)dstL * NMSG);
    const float4* B4  = (const float4*)(B + (size_t)src * NMSG);
    const float4* WE0 = (const float4*)(sWE);
    const float4* WE1 = (const float4*)(sWE + NMSG);

    u64 macc[CP2];
#pragma unroll
    for (int p = 0; p < CP2; p++) macc[p] = 0ull;

#pragma unroll 2
    for (int kg = 0; kg < NMSG / 4; kg++) {
        float4 a = A4[kg];
        float4 b = B4[kg];
        float4 u0 = WE0[kg];
        float4 u1 = WE1[kg];
        float h0 = fmaxf(fmaf(w.x, u0.x, fmaf(w.y, u1.x, a.x + b.x)), 0.f);
        float h1 = fmaxf(fmaf(w.x, u0.y, fmaf(w.y, u1.y, a.y + b.y)), 0.f);
        float h2 = fmaxf(fmaf(w.x, u0.z, fmaf(w.y, u1.z, a.z + b.z)), 0.f);
        float h3 = fmaxf(fmaf(w.x, u0.w, fmaf(w.y, u1.w, a.w + b.w)), 0.f);
        u64 h02 = pack2(h0), h12 = pack2(h1), h22 = pack2(h2), h32 = pack2(h3);

        const float4* r0 = (const float4*)(sWm2 + (4 * kg + 0) * CIP);
        const float4* r1 = (const float4*)(sWm2 + (4 * kg + 1) * CIP);
        const float4* r2 = (const float4*)(sWm2 + (4 * kg + 2) * CIP);
        const float4* r3 = (const float4*)(sWm2 + (4 * kg + 3) * CIP);
#pragma unroll
        for (int j = 0; j < C4; j++) {
            float4 q0 = r0[j], q1 = r1[j], q2 = r2[j], q3 = r3[j];
            u64 lo = macc[2 * j], hi = macc[2 * j + 1];
            lo = fma2(h02, pairf(q0.x, q0.y), lo);
            hi = fma2(h02, pairf(q0.z, q0.w), hi);
            lo = fma2(h12, pairf(q1.x, q1.y), lo);
            hi = fma2(h12, pairf(q1.z, q1.w), hi);
            lo = fma2(h22, pairf(q2.x, q2.y), lo);
            hi = fma2(h22, pairf(q2.z, q2.w), hi);
            lo = fma2(h32, pairf(q3.x, q3.y), lo);
            hi = fma2(h32, pairf(q3.z, q3.w), hi);
            macc[2 * j] = lo;
            macc[2 * j + 1] = hi;
        }
    }

    // t_c = (m_c + bm2_c) * (xi_c - xj_c)   (x rows are 8B aligned -> float2)
    float t[C_IN];
    {
        const float2* xd2 = (const float2*)(x + (size_t)dstL * C_IN);
        const float2* xs2 = (const float2*)(x + (size_t)src  * C_IN);
#pragma unroll
        for (int p = 0; p < C_IN / 2; p++) {
            float2 mp = unpack2(macc[p]);
            float2 xi = xd2[p];
            float2 xj = xs2[p];
            if (RELU_IN) {
                xi.x = fmaxf(xi.x, 0.f); xi.y = fmaxf(xi.y, 0.f);
                xj.x = fmaxf(xj.x, 0.f); xj.y = fmaxf(xj.y, 0.f);
            }
            t[2 * p]     = (mp.x + sbm2[2 * p])     * (xi.x - xj.x);
            t[2 * p + 1] = (mp.y + sbm2[2 * p + 1]) * (xi.y - xj.y);
        }
        if (!valid) {
#pragma unroll
            for (int c = 0; c < C_IN; c++) t[c] = 0.f;
        }
    }

    // warp-segmented inclusive scan by key (predicates computed once)
    bool pr[5];
#pragma unroll
    for (int r = 0; r < 5; r++) {
        int off = 1 << r;
        int ku = __shfl_up_sync(0xffffffffu, key, off);
        pr[r] = (lane >= off) && (ku == key);
    }
#pragma unroll
    for (int r = 0; r < 5; r++) {
        int off = 1 << r;
        bool p = pr[r];
#pragma unroll
        for (int c = 0; c < C_IN; c++) {
            float u = __shfl_up_sync(0xffffffffu, t[c], off);
            if (p) t[c] += u;
        }
    }
    int kn = __shfl_down_sync(0xffffffffu, key, 1);
    bool tail = (lane == 31) || (kn != key);
    if (valid && tail) {
        float* tp = Tagg + (size_t)dstL * TSTR;
#pragma unroll
        for (int c = 0; c < C_IN; c++) atomicAdd(tp + c, t[c]);
    }
}

// ---------------------------------------------------------------------------
// Host-side layer driver (hidden/output layers, C_IN=30)
// ---------------------------------------------------------------------------
template <int C_IN, int C_OUT, bool RELU_IN>
static void run_layer(const float* xin,
                      const float* const* W,   // W1,b1,Wm1,bm1,Wm2,bm2,W2,b2
                      const int* ssrc, const int* sdst, const float2* sw,
                      float* Abuf, float* Bbuf, float* Tbuf, const int* cnt,
                      float* xout,
                      int N, int E) {
    zeroT_kernel<<<(N * TSTR + 255) / 256, 256>>>(Tbuf, N * TSTR);
    precomp_ab_kernel<C_IN, RELU_IN><<<(N * NMSG + 255) / 256, 256>>>(
        xin, W[2], W[3], Abuf, Bbuf, N);
    edge_kernel<C_IN, RELU_IN><<<(E + 255) / 256, 256>>>(
        ssrc, sdst, sw, xin, Abuf, Bbuf, W[2], W[4], W[5], Tbuf, E);
    node_finish_kernel<C_IN, C_OUT, RELU_IN><<<(N * C_OUT + 255) / 256, 256>>>(
        xin, W[0], W[1], W[6], W[7], Tbuf, cnt, xout, N);
}

extern "C" void kernel_launch(void* const* d_in, const int* in_sizes, int n_in,
                              void* d_out, int out_size) {
    const float* feat  = (const float*)d_in[0];
    const void*  edges = d_in[1];
    const float* ew    = (const float*)d_in[2];

    const float* P[24];
    for (int i = 0; i < 24; i++) P[i] = (const float*)d_in[3 + i];
    // P[0..7] = layer d, P[8..15] = layer h, P[16..23] = layer o

    int N = in_sizes[0];        // NUM_IN == 1 -> element count == node count
    int E = in_sizes[2] / 2;    // weights is [E,2]

    float *x0, *x1, *A, *B, *T;
    int *ssrc, *sdst, *cnt;
    float2 *sw;
    cudaGetSymbolAddress((void**)&x0,   g_x0);
    cudaGetSymbolAddress((void**)&x1,   g_x1);
    cudaGetSymbolAddress((void**)&A,    g_A);
    cudaGetSymbolAddress((void**)&B,    g_B);
    cudaGetSymbolAddress((void**)&T,    g_T);
    cudaGetSymbolAddress((void**)&ssrc, g_ssrc);
    cudaGetSymbolAddress((void**)&sdst, g_sdst);
    cudaGetSymbolAddress((void**)&sw,   g_sw);
    cudaGetSymbolAddress((void**)&cnt,  g_cnt);

    // Preprocessing: dtype detect + counting sort by dst (parallel scan)
    int nb = (N + 1023) / 1024;
    detect_edges_kernel<<<1, 32>>>((const long long*)edges);
    zero_hist_kernel<<<(N + 255) / 256, 256>>>(N);
    hist_kernel<<<(E + 255) / 256, 256>>>(edges, E);
    scan1_kernel<<<nb, 1024>>>(N);
    scan2_kernel<<<1, 32>>>(nb);
    scan3_kernel<<<nb, 1024>>>(N);
    scatter_kernel<<<(E + 255) / 256, 256>>>(edges, ew, E);

    // d layer: scalar-x edge kernel, scalar t aggregation
    zeroT_kernel<<<(N * TSTR + 255) / 256, 256>>>(T, N * TSTR);
    edge_d_kernel<<<(E + 255) / 256, 256>>>(
        ssrc, sdst, sw, feat, P[2], P[3], P[4], P[5], T, E);
    node_finish_kernel<1, 30, false><<<(N * 30 + 255) / 256, 256>>>(
        feat, P[0], P[1], P[6], P[7], T, cnt, x0, N);

    // hidden layers (shared weights) + output layer
    run_layer<30, 30, true>(x0, P + 8,  ssrc, sdst, sw, A, B, T, cnt, x1, N, E);
    run_layer<30, 30, true>(x1, P + 8,  ssrc, sdst, sw, A, B, T, cnt, x0, N, E);
    run_layer<30, 30, true>(x0, P + 8,  ssrc, sdst, sw, A, B, T, cnt, x1, N, E);
    run_layer<30, 1, true>(x1,  P + 16, ssrc, sdst, sw, A, B, T, cnt, (float*)d_out, N, E);
}

// round 8
// speedup vs baseline: 2.0337x; 1.1783x over previous
#include <cuda_runtime.h>
#include <cuda_fp16.h>
#include <cstdint>

#define NN      50000
#define NE      800000
#define NMSG    200
#define BSTR    208           // fp16 B row stride (halves) -> 416B, 16B aligned
#define TSTR    32            // Tagg row stride (floats)

// ---------------------------------------------------------------------------
// Static device scratch
// ---------------------------------------------------------------------------
__device__ __align__(16) float  g_x0[NN * 30];
__device__ __align__(16) float  g_x1[NN * 30];
__device__ __align__(16) float  g_A [NN * NMSG];
__device__ __align__(16) __half g_Bh[NN * BSTR];
__device__ __align__(16) float  g_T [NN * TSTR];
__device__ int g_is64;
__device__ int g_cnt[NN];
__device__ int g_ofs[NN];
__device__ int g_bsum[64];
__device__ int g_xmaxi[8];     // per-layer max(relu(x)) as float bits (nonneg)
__device__ int g_ssrc[NE];
__device__ int g_sdst[NE];
__device__ __align__(8) float2 g_sw[NE];

// ---------------------------------------------------------------------------
// Packed f32x2 helpers
// ---------------------------------------------------------------------------
typedef unsigned long long u64;
__device__ __forceinline__ u64 fma2(u64 a, u64 b, u64 c) {
    u64 d; asm("fma.rn.f32x2 %0, %1, %2, %3;" : "=l"(d) : "l"(a), "l"(b), "l"(c)); return d;
}
__device__ __forceinline__ u64 pack2(float x) {
    u64 d; asm("mov.b64 %0, {%1, %1};" : "=l"(d) : "f"(x)); return d;
}
__device__ __forceinline__ u64 pairf(float lo, float hi) {
    u64 d; asm("mov.b64 %0, {%1, %2};" : "=l"(d) : "f"(lo), "f"(hi)); return d;
}
__device__ __forceinline__ float2 unpack2(u64 a) {
    float2 f; asm("mov.b64 {%0, %1}, %2;" : "=f"(f.x), "=f"(f.y) : "l"(a)); return f;
}

// ---------------------------------------------------------------------------
// Edge dtype detection
// ---------------------------------------------------------------------------
__global__ void detect_edges_kernel(const long long* __restrict__ e64) {
    if (threadIdx.x == 0 && blockIdx.x == 0) {
        int ok = 1;
        for (int i = 0; i < 16; i++) {
            long long v = e64[i];
            if (v < 0 || v >= NN) ok = 0;
        }
        g_is64 = ok;
    }
}
__device__ __forceinline__ int load_idx(const void* edges, long long pos, bool is64) {
    if (is64) return (int)((const long long*)edges)[pos];
    return ((const int*)edges)[pos];
}

// ---------------------------------------------------------------------------
// Counting sort by dst (parallel scan)
// ---------------------------------------------------------------------------
__global__ void zero_hist_kernel(int N) {
    int i = blockIdx.x * blockDim.x + threadIdx.x;
    if (i < N) g_cnt[i] = 0;
    if (i < 8) g_xmaxi[i] = 0;        // 0 bits == 0.0f
}
__global__ void hist_kernel(const void* __restrict__ edges, int E) {
    int e = blockIdx.x * blockDim.x + threadIdx.x;
    if (e >= E) return;
    bool is64 = (g_is64 != 0);
    atomicAdd(&g_cnt[load_idx(edges, (long long)E + e, is64)], 1);
}
__global__ void scan1_kernel(int N) {
    __shared__ int s[1024];
    int i = blockIdx.x * 1024 + threadIdx.x;
    int v = (i < N) ? g_cnt[i] : 0;
    s[threadIdx.x] = v;
    __syncthreads();
    for (int off = 1; off < 1024; off <<= 1) {
        int t = (threadIdx.x >= (unsigned)off) ? s[threadIdx.x - off] : 0;
        __syncthreads();
        s[threadIdx.x] += t;
        __syncthreads();
    }
    if (i < N) g_ofs[i] = s[threadIdx.x] - v;
    if (threadIdx.x == 1023) g_bsum[blockIdx.x] = s[1023];
}
__global__ void scan2_kernel(int nb) {
    if (threadIdx.x == 0 && blockIdx.x == 0) {
        int acc = 0;
        for (int b = 0; b < nb; b++) { int t = g_bsum[b]; g_bsum[b] = acc; acc += t; }
    }
}
__global__ void scan3_kernel(int N) {
    int i = blockIdx.x * 1024 + threadIdx.x;
    if (i < N) g_ofs[i] += g_bsum[blockIdx.x];
}
__global__ void scatter_kernel(const void* __restrict__ edges,
                               const float* __restrict__ ea, int E) {
    int e = blockIdx.x * blockDim.x + threadIdx.x;
    if (e >= E) return;
    bool is64 = (g_is64 != 0);
    int src = load_idx(edges, e, is64);
    int dst = load_idx(edges, (long long)E + e, is64);
    int p = atomicAdd(&g_ofs[dst], 1);
    g_ssrc[p] = src;
    g_sdst[p] = dst;
    g_sw[p]   = ((const float2*)ea)[e];
}

__global__ void zeroT_kernel(float* __restrict__ T, int n) {
    int i = blockIdx.x * blockDim.x + threadIdx.x;
    if (i < n) T[i] = 0.f;
}

// ---------------------------------------------------------------------------
// Per-node precompute (C_IN=30): A fp32; B fp16 scaled by 256/xmax
// ---------------------------------------------------------------------------
template <int C_IN, bool RELU_IN>
__global__ void precomp_ab_kernel(const float* __restrict__ x,
                                  const float* __restrict__ Wm1,
                                  const float* __restrict__ bm1,
                                  float* __restrict__ A,
                                  __half* __restrict__ Bh,
                                  const int* __restrict__ xmaxi,
                                  int N) {
    int idx = blockIdx.x * blockDim.x + threadIdx.x;
    if (idx >= N * NMSG) return;
    float xmax = __int_as_float(*xmaxi);
    float bs = (xmax > 0.f) ? 256.f / xmax : 1.f;
    int n = idx / NMSG;
    int k = idx - n * NMSG;
    float a = bm1[k];
    float b = 0.f;
#pragma unroll
    for (int c = 0; c < C_IN; c++) {
        float xv = x[(size_t)n * C_IN + c];
        if (RELU_IN) xv = fmaxf(xv, 0.f);
        a = fmaf(xv, Wm1[c * NMSG + k], a);
        b = fmaf(xv, Wm1[(C_IN + c) * NMSG + k], b);
    }
    A[idx] = a;
    Bh[(size_t)n * BSTR + k] = __float2half_rn(b * bs);
}

// ---------------------------------------------------------------------------
// Node finish: out = b1 + deg*b2 + x@W1 + Tagg@W2; also records max(relu(out))
// ---------------------------------------------------------------------------
template <int C_IN, int C_OUT, bool RELU_IN>
__global__ void node_finish_kernel(const float* __restrict__ x,
                                   const float* __restrict__ W1,
                                   const float* __restrict__ b1,
                                   const float* __restrict__ W2,
                                   const float* __restrict__ b2,
                                   const float* __restrict__ Tagg,
                                   const int* __restrict__ cnt,
                                   float* __restrict__ out,
                                   int* __restrict__ xmax_out,   // nullable
                                   int N) {
    int idx = blockIdx.x * blockDim.x + threadIdx.x;
    float v = 0.f;
    bool inb = (idx < N * C_OUT);
    if (inb) {
        int n  = idx / C_OUT;
        int co = idx - n * C_OUT;
        v = b1[co] + (float)cnt[n] * b2[co];
#pragma unroll
        for (int c = 0; c < C_IN; c++) {
            float xv = x[(size_t)n * C_IN + c];
            if (RELU_IN) xv = fmaxf(xv, 0.f);
            v = fmaf(xv, W1[c * C_OUT + co], v);
            v = fmaf(Tagg[(size_t)n * TSTR + c], W2[c * C_OUT + co], v);
        }
        out[idx] = v;
    }
    if (xmax_out != nullptr) {
        float lv = inb ? fmaxf(v, 0.f) : 0.f;
#pragma unroll
        for (int off = 16; off > 0; off >>= 1)
            lv = fmaxf(lv, __shfl_xor_sync(0xffffffffu, lv, off));
        __shared__ float wmax[8];
        int lane = threadIdx.x & 31, warp = threadIdx.x >> 5;
        if (lane == 0) wmax[warp] = lv;
        __syncthreads();
        if (threadIdx.x == 0) {
            float bm = wmax[0];
#pragma unroll
            for (int i = 1; i < 8; i++) bm = fmaxf(bm, wmax[i]);
            atomicMax(xmax_out, __float_as_int(bm));   // nonneg: int order == float order
        }
    }
}

// ---------------------------------------------------------------------------
// d-layer edge kernel (C_IN=1): scalar t, segmented-scan aggregation
// ---------------------------------------------------------------------------
__global__ void __launch_bounds__(256)
edge_d_kernel(const int* __restrict__ srcArr,
              const int* __restrict__ dstArr,
              const float2* __restrict__ wArr,
              const float* __restrict__ x,
              const float* __restrict__ Wm1,
              const float* __restrict__ bm1,
              const float* __restrict__ Wm2,
              const float* __restrict__ bm2,
              float* __restrict__ Tagg,
              int E) {
    __shared__ __align__(16) float sW0[NMSG], sW1[NMSG], sE0[NMSG], sE1[NMSG];
    __shared__ __align__(16) float sB1[NMSG], sM2[NMSG];
    __shared__ float sbm2s;

    const int tid = threadIdx.x;
    for (int i = tid; i < NMSG; i += 256) {
        sW0[i] = Wm1[0 * NMSG + i];
        sW1[i] = Wm1[1 * NMSG + i];
        sE0[i] = Wm1[2 * NMSG + i];
        sE1[i] = Wm1[3 * NMSG + i];
        sB1[i] = bm1[i];
        sM2[i] = Wm2[i];
    }
    if (tid == 0) sbm2s = bm2[0];
    __syncthreads();

    const int e = blockIdx.x * 256 + tid;
    const bool valid = (e < E);
    const int lane = tid & 31;

    int src = 0, dstL = 0, key = -1;
    float2 w = make_float2(0.f, 0.f);
    if (valid) {
        src  = srcArr[e];
        dstL = dstArr[e];
        key  = dstL;
        w    = wArr[e];
    }
    const float xi = x[dstL];
    const float xj = x[src];

    float m = 0.f;
#pragma unroll 2
    for (int g = 0; g < NMSG / 4; g++) {
        float4 w0 = ((const float4*)sW0)[g];
        float4 w1 = ((const float4*)sW1)[g];
        float4 e0 = ((const float4*)sE0)[g];
        float4 e1 = ((const float4*)sE1)[g];
        float4 bb = ((const float4*)sB1)[g];
        float4 m2 = ((const float4*)sM2)[g];
        float h0 = fmaxf(fmaf(xi, w0.x, fmaf(xj, w1.x, fmaf(w.x, e0.x, fmaf(w.y, e1.x, bb.x)))), 0.f);
        float h1 = fmaxf(fmaf(xi, w0.y, fmaf(xj, w1.y, fmaf(w.x, e0.y, fmaf(w.y, e1.y, bb.y)))), 0.f);
        float h2 = fmaxf(fmaf(xi, w0.z, fmaf(xj, w1.z, fmaf(w.x, e0.z, fmaf(w.y, e1.z, bb.z)))), 0.f);
        float h3 = fmaxf(fmaf(xi, w0.w, fmaf(xj, w1.w, fmaf(w.x, e0.w, fmaf(w.y, e1.w, bb.w)))), 0.f);
        m = fmaf(h0, m2.x, fmaf(h1, m2.y, fmaf(h2, m2.z, fmaf(h3, m2.w, m))));
    }

    float t = valid ? (m + sbm2s) * (xi - xj) : 0.f;

#pragma unroll
    for (int r = 0; r < 5; r++) {
        int off = 1 << r;
        int ku = __shfl_up_sync(0xffffffffu, key, off);
        float tu = __shfl_up_sync(0xffffffffu, t, off);
        if (lane >= off && ku == key) t += tu;
    }
    int kn = __shfl_down_sync(0xffffffffu, key, 1);
    bool tail = (lane == 31) || (kn != key);
    if (valid && tail) atomicAdd(Tagg + (size_t)dstL * TSTR, t);
}

// ---------------------------------------------------------------------------
// Hidden/output edge kernel (C_IN=30): 2 edges/thread, scaled-fp16 B,
// f32x2 GEMV, warp-segmented reduction per edge set.
// ---------------------------------------------------------------------------
template <int C_IN, bool RELU_IN>
__global__ void __launch_bounds__(256)
edge_kernel(const int* __restrict__ srcArr,
            const int* __restrict__ dstArr,
            const float2* __restrict__ wArr,
            const float* __restrict__ x,
            const float* __restrict__ A,
            const __half* __restrict__ Bh,
            const float* __restrict__ Wm1,
            const float* __restrict__ Wm2,
            const float* __restrict__ bm2,
            const int* __restrict__ xmaxi,
            float* __restrict__ Tagg,
            int E) {
    constexpr int C4  = (C_IN + 3) / 4;      // 8
    constexpr int CIP = C4 * 4;              // 32
    constexpr int CP2 = CIP / 2;             // 16

    __shared__ __align__(16) float sWE[2 * NMSG];
    __shared__ __align__(16) float sWm2[NMSG * CIP];
    __shared__ float sbm2[CIP];

    const int tid = threadIdx.x;
    for (int i = tid; i < 2 * NMSG; i += 256) sWE[i] = Wm1[2 * C_IN * NMSG + i];
    for (int i = tid; i < NMSG * CIP; i += 256) {
        int k = i / CIP, c = i - k * CIP;
        sWm2[i] = (c < C_IN) ? Wm2[k * C_IN + c] : 0.f;
    }
    for (int i = tid; i < CIP; i += 256) sbm2[i] = (i < C_IN) ? bm2[i] : 0.f;
    __syncthreads();

    const float xmax = __int_as_float(*xmaxi);
    const float binv = (xmax > 0.f) ? xmax * (1.f / 256.f) : 1.f;

    const int base = blockIdx.x * 512;
    const int lane = tid & 31;

    int e[2], src[2], dstL[2], key[2];
    float2 w[2];
    bool valid[2];
#pragma unroll
    for (int s = 0; s < 2; s++) {
        e[s] = base + 256 * s + tid;
        valid[s] = (e[s] < E);
        src[s] = 0; dstL[s] = 0; key[s] = -1;
        w[s] = make_float2(0.f, 0.f);
        if (valid[s]) {
            src[s]  = srcArr[e[s]];
            dstL[s] = dstArr[e[s]];
            key[s]  = dstL[s];
            w[s]    = wArr[e[s]];
        }
    }

    const float4* A40 = (const float4*)(A + (size_t)dstL[0] * NMSG);
    const float4* A41 = (const float4*)(A + (size_t)dstL[1] * NMSG);
    const uint4*  B80 = (const uint4*)(Bh + (size_t)src[0] * BSTR);
    const uint4*  B81 = (const uint4*)(Bh + (size_t)src[1] * BSTR);
    const float4* WE0 = (const float4*)(sWE);
    const float4* WE1 = (const float4*)(sWE + NMSG);

    u64 m0[CP2], m1[CP2];
#pragma unroll
    for (int p = 0; p < CP2; p++) { m0[p] = 0ull; m1[p] = 0ull; }

#pragma unroll 1
    for (int kq = 0; kq < NMSG / 8; kq++) {      // 25 iterations, 8 k's each
        uint4 br0 = B80[kq];
        uint4 br1 = B81[kq];
        float bf0[8], bf1[8];
        {
            float2 f;
            f = __half22float2(*(const __half2*)&br0.x); bf0[0] = f.x; bf0[1] = f.y;
            f = __half22float2(*(const __half2*)&br0.y); bf0[2] = f.x; bf0[3] = f.y;
            f = __half22float2(*(const __half2*)&br0.z); bf0[4] = f.x; bf0[5] = f.y;
            f = __half22float2(*(const __half2*)&br0.w); bf0[6] = f.x; bf0[7] = f.y;
            f = __half22float2(*(const __half2*)&br1.x); bf1[0] = f.x; bf1[1] = f.y;
            f = __half22float2(*(const __half2*)&br1.y); bf1[2] = f.x; bf1[3] = f.y;
            f = __half22float2(*(const __half2*)&br1.z); bf1[4] = f.x; bf1[5] = f.y;
            f = __half22float2(*(const __half2*)&br1.w); bf1[6] = f.x; bf1[7] = f.y;
        }
#pragma unroll
        for (int sub = 0; sub < 2; sub++) {
            const int kg = kq * 2 + sub;
            float4 a0 = A40[kg];
            float4 a1 = A41[kg];
            float4 u0 = WE0[kg];
            float4 u1 = WE1[kg];
            float h0[4], h1[4];
            h0[0] = fmaxf(fmaf(w[0].x, u0.x, fmaf(w[0].y, u1.x, fmaf(bf0[4*sub+0], binv, a0.x))), 0.f);
            h0[1] = fmaxf(fmaf(w[0].x, u0.y, fmaf(w[0].y, u1.y, fmaf(bf0[4*sub+1], binv, a0.y))), 0.f);
            h0[2] = fmaxf(fmaf(w[0].x, u0.z, fmaf(w[0].y, u1.z, fmaf(bf0[4*sub+2], binv, a0.z))), 0.f);
            h0[3] = fmaxf(fmaf(w[0].x, u0.w, fmaf(w[0].y, u1.w, fmaf(bf0[4*sub+3], binv, a0.w))), 0.f);
            h1[0] = fmaxf(fmaf(w[1].x, u0.x, fmaf(w[1].y, u1.x, fmaf(bf1[4*sub+0], binv, a1.x))), 0.f);
            h1[1] = fmaxf(fmaf(w[1].x, u0.y, fmaf(w[1].y, u1.y, fmaf(bf1[4*sub+1], binv, a1.y))), 0.f);
            h1[2] = fmaxf(fmaf(w[1].x, u0.z, fmaf(w[1].y, u1.z, fmaf(bf1[4*sub+2], binv, a1.z))), 0.f);
            h1[3] = fmaxf(fmaf(w[1].x, u0.w, fmaf(w[1].y, u1.w, fmaf(bf1[4*sub+3], binv, a1.w))), 0.f);
            u64 h0p[4] = { pack2(h0[0]), pack2(h0[1]), pack2(h0[2]), pack2(h0[3]) };
            u64 h1p[4] = { pack2(h1[0]), pack2(h1[1]), pack2(h1[2]), pack2(h1[3]) };

#pragma unroll
            for (int r = 0; r < 4; r++) {
                const float4* row = (const float4*)(sWm2 + (4 * kg + r) * CIP);
#pragma unroll
                for (int j = 0; j < C4; j++) {
                    float4 q = row[j];
                    u64 qlo = pairf(q.x, q.y);
                    u64 qhi = pairf(q.z, q.w);
                    m0[2 * j]     = fma2(h0p[r], qlo, m0[2 * j]);
                    m0[2 * j + 1] = fma2(h0p[r], qhi, m0[2 * j + 1]);
                    m1[2 * j]     = fma2(h1p[r], qlo, m1[2 * j]);
                    m1[2 * j + 1] = fma2(h1p[r], qhi, m1[2 * j + 1]);
                }
            }
        }
    }

    // Per edge set: t = (m + bm2) * (xi - xj), segmented scan, tail atomics
#pragma unroll
    for (int s = 0; s < 2; s++) {
        float t[C_IN];
        {
            const float2* xd2 = (const float2*)(x + (size_t)dstL[s] * C_IN);
            const float2* xs2 = (const float2*)(x + (size_t)src[s]  * C_IN);
            u64* mm = (s == 0) ? m0 : m1;
#pragma unroll
            for (int p = 0; p < C_IN / 2; p++) {
                float2 mp = unpack2(mm[p]);
                float2 xi = xd2[p];
                float2 xj = xs2[p];
                if (RELU_IN) {
                    xi.x = fmaxf(xi.x, 0.f); xi.y = fmaxf(xi.y, 0.f);
                    xj.x = fmaxf(xj.x, 0.f); xj.y = fmaxf(xj.y, 0.f);
                }
                t[2 * p]     = (mp.x + sbm2[2 * p])     * (xi.x - xj.x);
                t[2 * p + 1] = (mp.y + sbm2[2 * p + 1]) * (xi.y - xj.y);
            }
            if (!valid[s]) {
#pragma unroll
                for (int c = 0; c < C_IN; c++) t[c] = 0.f;
            }
        }

        bool pr[5];
#pragma unroll
        for (int r = 0; r < 5; r++) {
            int off = 1 << r;
            int ku = __shfl_up_sync(0xffffffffu, key[s], off);
            pr[r] = (lane >= off) && (ku == key[s]);
        }
#pragma unroll
        for (int r = 0; r < 5; r++) {
            int off = 1 << r;
            bool p = pr[r];
#pragma unroll
            for (int c = 0; c < C_IN; c++) {
                float u = __shfl_up_sync(0xffffffffu, t[c], off);
                if (p) t[c] += u;
            }
        }
        int kn = __shfl_down_sync(0xffffffffu, key[s], 1);
        bool tail = (lane == 31) || (kn != key[s]);
        if (valid[s] && tail) {
            float* tp = Tagg + (size_t)dstL[s] * TSTR;
#pragma unroll
            for (int c = 0; c < C_IN; c++) atomicAdd(tp + c, t[c]);
        }
    }
}

// ---------------------------------------------------------------------------
// Host-side layer driver (C_IN=30 layers)
// ---------------------------------------------------------------------------
template <int C_IN, int C_OUT, bool RELU_IN>
static void run_layer(const float* xin,
                      const float* const* W,   // W1,b1,Wm1,bm1,Wm2,bm2,W2,b2
                      const int* ssrc, const int* sdst, const float2* sw,
                      float* Abuf, __half* Bbuf, float* Tbuf, const int* cnt,
                      const int* xmax_in, int* xmax_out,
                      float* xout,
                      int N, int E) {
    zeroT_kernel<<<(N * TSTR + 255) / 256, 256>>>(Tbuf, N * TSTR);
    precomp_ab_kernel<C_IN, RELU_IN><<<(N * NMSG + 255) / 256, 256>>>(
        xin, W[2], W[3], Abuf, Bbuf, xmax_in, N);
    edge_kernel<C_IN, RELU_IN><<<(E + 511) / 512, 256>>>(
        ssrc, sdst, sw, xin, Abuf, Bbuf, W[2], W[4], W[5], xmax_in, Tbuf, E);
    node_finish_kernel<C_IN, C_OUT, RELU_IN><<<(N * C_OUT + 255) / 256, 256>>>(
        xin, W[0], W[1], W[6], W[7], Tbuf, cnt, xout, xmax_out, N);
}

extern "C" void kernel_launch(void* const* d_in, const int* in_sizes, int n_in,
                              void* d_out, int out_size) {
    const float* feat  = (const float*)d_in[0];
    const void*  edges = d_in[1];
    const float* ew    = (const float*)d_in[2];

    const float* P[24];
    for (int i = 0; i < 24; i++) P[i] = (const float*)d_in[3 + i];
    // P[0..7] = layer d, P[8..15] = layer h, P[16..23] = layer o

    int N = in_sizes[0];
    int E = in_sizes[2] / 2;

    float *x0, *x1, *A, *T;
    __half *Bh;
    int *ssrc, *sdst, *cnt, *xm;
    float2 *sw;
    cudaGetSymbolAddress((void**)&x0,   g_x0);
    cudaGetSymbolAddress((void**)&x1,   g_x1);
    cudaGetSymbolAddress((void**)&A,    g_A);
    cudaGetSymbolAddress((void**)&Bh,   g_Bh);
    cudaGetSymbolAddress((void**)&T,    g_T);
    cudaGetSymbolAddress((void**)&ssrc, g_ssrc);
    cudaGetSymbolAddress((void**)&sdst, g_sdst);
    cudaGetSymbolAddress((void**)&sw,   g_sw);
    cudaGetSymbolAddress((void**)&cnt,  g_cnt);
    cudaGetSymbolAddress((void**)&xm,   g_xmaxi);

    // Preprocessing: dtype detect + counting sort by dst (parallel scan)
    int nb = (N + 1023) / 1024;
    detect_edges_kernel<<<1, 32>>>((const long long*)edges);
    zero_hist_kernel<<<(N + 255) / 256, 256>>>(N);
    hist_kernel<<<(E + 255) / 256, 256>>>(edges, E);
    scan1_kernel<<<nb, 1024>>>(N);
    scan2_kernel<<<1, 32>>>(nb);
    scan3_kernel<<<nb, 1024>>>(N);
    scatter_kernel<<<(E + 255) / 256, 256>>>(edges, ew, E);

    // d layer: scalar-x edge kernel; node_finish records xmax of relu(x0) -> xm[0]
    zeroT_kernel<<<(N * TSTR + 255) / 256, 256>>>(T, N * TSTR);
    edge_d_kernel<<<(E + 255) / 256, 256>>>(
        ssrc, sdst, sw, feat, P[2], P[3], P[4], P[5], T, E);
    node_finish_kernel<1, 30, false><<<(N * 30 + 255) / 256, 256>>>(
        feat, P[0], P[1], P[6], P[7], T, cnt, x0, xm + 0, N);

    // hidden layers (shared weights) + output layer
    run_layer<30, 30, true>(x0, P + 8,  ssrc, sdst, sw, A, Bh, T, cnt, xm + 0, xm + 1, x1, N, E);
    run_layer<30, 30, true>(x1, P + 8,  ssrc, sdst, sw, A, Bh, T, cnt, xm + 1, xm + 2, x0, N, E);
    run_layer<30, 30, true>(x0, P + 8,  ssrc, sdst, sw, A, Bh, T, cnt, xm + 2, xm + 3, x1, N, E);
    run_layer<30, 1, true>(x1,  P + 16, ssrc, sdst, sw, A, Bh, T, cnt, xm + 3, nullptr,
                           (float*)d_out, N, E);
}

// round 10
// speedup vs baseline: 2.1811x; 1.0725x over previous
#include <cuda_runtime.h>
#include <cuda_fp16.h>
#include <cstdint>

#define NN      50000
#define NE      800000
#define NMSG    200
#define BSTR    208           // fp16 B row stride (halves) -> 416B, 16B aligned
#define TSTR    32            // Tagg row stride (floats)

// ---------------------------------------------------------------------------
// Static device scratch
// ---------------------------------------------------------------------------
__device__ __align__(16) float  g_x0[NN * 30];
__device__ __align__(16) float  g_x1[NN * 30];
__device__ __align__(16) float  g_A [NN * NMSG];
__device__ __align__(16) __half g_Bh[NN * BSTR];
__device__ __align__(16) float  g_T [NN * TSTR];
__device__ int g_is64;
__device__ int g_cnt[NN];
__device__ int g_ofs[NN];
__device__ int g_bsum[64];
__device__ int g_xmaxi[8];     // per-layer max(relu(x)) as float bits (nonneg)
__device__ int g_ssrc[NE];
__device__ int g_sdst[NE];
__device__ __align__(8) float2 g_sw[NE];

// ---------------------------------------------------------------------------
// Packed f32x2 helpers
// ---------------------------------------------------------------------------
typedef unsigned long long u64;
__device__ __forceinline__ u64 fma2(u64 a, u64 b, u64 c) {
    u64 d; asm("fma.rn.f32x2 %0, %1, %2, %3;" : "=l"(d) : "l"(a), "l"(b), "l"(c)); return d;
}
__device__ __forceinline__ u64 pack2(float x) {
    u64 d; asm("mov.b64 %0, {%1, %1};" : "=l"(d) : "f"(x)); return d;
}
__device__ __forceinline__ u64 pairf(float lo, float hi) {
    u64 d; asm("mov.b64 %0, {%1, %2};" : "=l"(d) : "f"(lo), "f"(hi)); return d;
}
__device__ __forceinline__ float2 unpack2(u64 a) {
    float2 f; asm("mov.b64 {%0, %1}, %2;" : "=f"(f.x), "=f"(f.y) : "l"(a)); return f;
}

// ---------------------------------------------------------------------------
// Edge dtype detection
// ---------------------------------------------------------------------------
__global__ void detect_edges_kernel(const long long* __restrict__ e64) {
    if (threadIdx.x == 0 && blockIdx.x == 0) {
        int ok = 1;
        for (int i = 0; i < 16; i++) {
            long long v = e64[i];
            if (v < 0 || v >= NN) ok = 0;
        }
        g_is64 = ok;
    }
}
__device__ __forceinline__ int load_idx(const void* edges, long long pos, bool is64) {
    if (is64) return (int)((const long long*)edges)[pos];
    return ((const int*)edges)[pos];
}

// ---------------------------------------------------------------------------
// Counting sort by dst (parallel scan)
// ---------------------------------------------------------------------------
__global__ void zero_hist_kernel(int N) {
    int i = blockIdx.x * blockDim.x + threadIdx.x;
    if (i < N) g_cnt[i] = 0;
    if (i < 8) g_xmaxi[i] = 0;        // 0 bits == 0.0f
}
__global__ void hist_kernel(const void* __restrict__ edges, int E) {
    int e = blockIdx.x * blockDim.x + threadIdx.x;
    if (e >= E) return;
    bool is64 = (g_is64 != 0);
    atomicAdd(&g_cnt[load_idx(edges, (long long)E + e, is64)], 1);
}
__global__ void scan1_kernel(int N) {
    __shared__ int s[1024];
    int i = blockIdx.x * 1024 + threadIdx.x;
    int v = (i < N) ? g_cnt[i] : 0;
    s[threadIdx.x] = v;
    __syncthreads();
    for (int off = 1; off < 1024; off <<= 1) {
        int t = (threadIdx.x >= (unsigned)off) ? s[threadIdx.x - off] : 0;
        __syncthreads();
        s[threadIdx.x] += t;
        __syncthreads();
    }
    if (i < N) g_ofs[i] = s[threadIdx.x] - v;
    if (threadIdx.x == 1023) g_bsum[blockIdx.x] = s[1023];
}
__global__ void scan2_kernel(int nb) {
    if (threadIdx.x == 0 && blockIdx.x == 0) {
        int acc = 0;
        for (int b = 0; b < nb; b++) { int t = g_bsum[b]; g_bsum[b] = acc; acc += t; }
    }
}
__global__ void scan3_kernel(int N) {
    int i = blockIdx.x * 1024 + threadIdx.x;
    if (i < N) g_ofs[i] += g_bsum[blockIdx.x];
}
__global__ void scatter_kernel(const void* __restrict__ edges,
                               const float* __restrict__ ea, int E) {
    int e = blockIdx.x * blockDim.x + threadIdx.x;
    if (e >= E) return;
    bool is64 = (g_is64 != 0);
    int src = load_idx(edges, e, is64);
    int dst = load_idx(edges, (long long)E + e, is64);
    int p = atomicAdd(&g_ofs[dst], 1);
    g_ssrc[p] = src;
    g_sdst[p] = dst;
    g_sw[p]   = ((const float2*)ea)[e];
}

__global__ void zeroT_kernel(float* __restrict__ T, int n) {
    int i = blockIdx.x * blockDim.x + threadIdx.x;
    if (i < n) T[i] = 0.f;
}

// ---------------------------------------------------------------------------
// Per-node precompute, vectorized (4 k's per thread):
//   A[n,k] = relu?(x)·Wm1[0:C,k] + bm1[k]  (fp32)
//   B[n,k] = relu?(x)·Wm1[C:2C,k]          (fp16, scaled by 256/xmax)
// Also zeroes Tagg (grid covers N*TSTR).
// ---------------------------------------------------------------------------
template <int C_IN, bool RELU_IN>
__global__ void precomp_ab_kernel(const float* __restrict__ x,
                                  const float* __restrict__ Wm1,
                                  const float* __restrict__ bm1,
                                  float* __restrict__ A,
                                  __half* __restrict__ Bh,
                                  const int* __restrict__ xmaxi,
                                  float* __restrict__ Tagg,
                                  int N) {
    int idx = blockIdx.x * blockDim.x + threadIdx.x;
    if (idx < N * TSTR) Tagg[idx] = 0.f;
    if (idx >= N * (NMSG / 4)) return;
    int n  = idx / (NMSG / 4);
    int kq = idx - n * (NMSG / 4);

    float xmax = __int_as_float(*xmaxi);
    float bs = (xmax > 0.f) ? 256.f / xmax : 1.f;

    float4 a = ((const float4*)bm1)[kq];
    float4 b = make_float4(0.f, 0.f, 0.f, 0.f);
#pragma unroll
    for (int c = 0; c < C_IN; c++) {
        float xv = x[(size_t)n * C_IN + c];
        if (RELU_IN) xv = fmaxf(xv, 0.f);
        float4 wa = ((const float4*)(Wm1 + c * NMSG))[kq];
        float4 wb = ((const float4*)(Wm1 + (C_IN + c) * NMSG))[kq];
        a.x = fmaf(xv, wa.x, a.x); a.y = fmaf(xv, wa.y, a.y);
        a.z = fmaf(xv, wa.z, a.z); a.w = fmaf(xv, wa.w, a.w);
        b.x = fmaf(xv, wb.x, b.x); b.y = fmaf(xv, wb.y, b.y);
        b.z = fmaf(xv, wb.z, b.z); b.w = fmaf(xv, wb.w, b.w);
    }
    ((float4*)(A + (size_t)n * NMSG))[kq] = a;
    __half2 b01 = __floats2half2_rn(b.x * bs, b.y * bs);
    __half2 b23 = __floats2half2_rn(b.z * bs, b.w * bs);
    __half2* bp = (__half2*)(Bh + (size_t)n * BSTR + kq * 4);
    bp[0] = b01; bp[1] = b23;
}

// ---------------------------------------------------------------------------
// Node finish: out = b1 + deg*b2 + x@W1 + Tagg@W2; also records max(relu(out))
// ---------------------------------------------------------------------------
template <int C_IN, int C_OUT, bool RELU_IN>
__global__ void node_finish_kernel(const float* __restrict__ x,
                                   const float* __restrict__ W1,
                                   const float* __restrict__ b1,
                                   const float* __restrict__ W2,
                                   const float* __restrict__ b2,
                                   const float* __restrict__ Tagg,
                                   const int* __restrict__ cnt,
                                   float* __restrict__ out,
                                   int* __restrict__ xmax_out,   // nullable
                                   int N) {
    int idx = blockIdx.x * blockDim.x + threadIdx.x;
    float v = 0.f;
    bool inb = (idx < N * C_OUT);
    if (inb) {
        int n  = idx / C_OUT;
        int co = idx - n * C_OUT;
        v = b1[co] + (float)cnt[n] * b2[co];
#pragma unroll
        for (int c = 0; c < C_IN; c++) {
            float xv = x[(size_t)n * C_IN + c];
            if (RELU_IN) xv = fmaxf(xv, 0.f);
            v = fmaf(xv, W1[c * C_OUT + co], v);
            v = fmaf(Tagg[(size_t)n * TSTR + c], W2[c * C_OUT + co], v);
        }
        out[idx] = v;
    }
    if (xmax_out != nullptr) {
        float lv = inb ? fmaxf(v, 0.f) : 0.f;
#pragma unroll
        for (int off = 16; off > 0; off >>= 1)
            lv = fmaxf(lv, __shfl_xor_sync(0xffffffffu, lv, off));
        __shared__ float wmax[8];
        int lane = threadIdx.x & 31, warp = threadIdx.x >> 5;
        if (lane == 0) wmax[warp] = lv;
        __syncthreads();
        if (threadIdx.x == 0) {
            float bm = wmax[0];
#pragma unroll
            for (int i = 1; i < 8; i++) bm = fmaxf(bm, wmax[i]);
            atomicMax(xmax_out, __float_as_int(bm));   // nonneg: int order == float order
        }
    }
}

// ---------------------------------------------------------------------------
// d-layer edge kernel (C_IN=1): scalar t, segmented-scan aggregation
// ---------------------------------------------------------------------------
__global__ void __launch_bounds__(256)
edge_d_kernel(const int* __restrict__ srcArr,
              const int* __restrict__ dstArr,
              const float2* __restrict__ wArr,
              const float* __restrict__ x,
              const float* __restrict__ Wm1,
              const float* __restrict__ bm1,
              const float* __restrict__ Wm2,
              const float* __restrict__ bm2,
              float* __restrict__ Tagg,
              int E) {
    __shared__ __align__(16) float sW0[NMSG], sW1[NMSG], sE0[NMSG], sE1[NMSG];
    __shared__ __align__(16) float sB1[NMSG], sM2[NMSG];
    __shared__ float sbm2s;

    const int tid = threadIdx.x;
    for (int i = tid; i < NMSG; i += 256) {
        sW0[i] = Wm1[0 * NMSG + i];
        sW1[i] = Wm1[1 * NMSG + i];
        sE0[i] = Wm1[2 * NMSG + i];
        sE1[i] = Wm1[3 * NMSG + i];
        sB1[i] = bm1[i];
        sM2[i] = Wm2[i];
    }
    if (tid == 0) sbm2s = bm2[0];
    __syncthreads();

    const int e = blockIdx.x * 256 + tid;
    const bool valid = (e < E);
    const int lane = tid & 31;

    int src = 0, dstL = 0, key = -1;
    float2 w = make_float2(0.f, 0.f);
    if (valid) {
        src  = srcArr[e];
        dstL = dstArr[e];
        key  = dstL;
        w    = wArr[e];
    }
    const float xi = x[dstL];
    const float xj = x[src];

    float m = 0.f;
#pragma unroll 2
    for (int g = 0; g < NMSG / 4; g++) {
        float4 w0 = ((const float4*)sW0)[g];
        float4 w1 = ((const float4*)sW1)[g];
        float4 e0 = ((const float4*)sE0)[g];
        float4 e1 = ((const float4*)sE1)[g];
        float4 bb = ((const float4*)sB1)[g];
        float4 m2 = ((const float4*)sM2)[g];
        float h0 = fmaxf(fmaf(xi, w0.x, fmaf(xj, w1.x, fmaf(w.x, e0.x, fmaf(w.y, e1.x, bb.x)))), 0.f);
        float h1 = fmaxf(fmaf(xi, w0.y, fmaf(xj, w1.y, fmaf(w.x, e0.y, fmaf(w.y, e1.y, bb.y)))), 0.f);
        float h2 = fmaxf(fmaf(xi, w0.z, fmaf(xj, w1.z, fmaf(w.x, e0.z, fmaf(w.y, e1.z, bb.z)))), 0.f);
        float h3 = fmaxf(fmaf(xi, w0.w, fmaf(xj, w1.w, fmaf(w.x, e0.w, fmaf(w.y, e1.w, bb.w)))), 0.f);
        m = fmaf(h0, m2.x, fmaf(h1, m2.y, fmaf(h2, m2.z, fmaf(h3, m2.w, m))));
    }

    float t = valid ? (m + sbm2s) * (xi - xj) : 0.f;

#pragma unroll
    for (int r = 0; r < 5; r++) {
        int off = 1 << r;
        int ku = __shfl_up_sync(0xffffffffu, key, off);
        float tu = __shfl_up_sync(0xffffffffu, t, off);
        if (lane >= off && ku == key) t += tu;
    }
    int kn = __shfl_down_sync(0xffffffffu, key, 1);
    bool tail = (lane == 31) || (kn != key);
    if (valid && tail) atomicAdd(Tagg + (size_t)dstL * TSTR, t);
}

// ---------------------------------------------------------------------------
// Hidden/output edge kernel (C_IN=30): 2 edges/thread, fp32 A + scaled-fp16 B,
// f32x2 GEMV, warp-segmented reduction per edge set.  (R8-validated)
// ---------------------------------------------------------------------------
template <int C_IN, bool RELU_IN>
__global__ void __launch_bounds__(256)
edge_kernel(const int* __restrict__ srcArr,
            const int* __restrict__ dstArr,
            const float2* __restrict__ wArr,
            const float* __restrict__ x,
            const float* __restrict__ A,
            const __half* __restrict__ Bh,
            const float* __restrict__ Wm1,
            const float* __restrict__ Wm2,
            const float* __restrict__ bm2,
            const int* __restrict__ xmaxi,
            float* __restrict__ Tagg,
            int E) {
    constexpr int C4  = (C_IN + 3) / 4;      // 8
    constexpr int CIP = C4 * 4;              // 32
    constexpr int CP2 = CIP / 2;             // 16

    __shared__ __align__(16) float sWE[2 * NMSG];
    __shared__ __align__(16) float sWm2[NMSG * CIP];
    __shared__ float sbm2[CIP];

    const int tid = threadIdx.x;
    for (int i = tid; i < 2 * NMSG; i += 256) sWE[i] = Wm1[2 * C_IN * NMSG + i];
    for (int i = tid; i < NMSG * CIP; i += 256) {
        int k = i / CIP, c = i - k * CIP;
        sWm2[i] = (c < C_IN) ? Wm2[k * C_IN + c] : 0.f;
    }
    for (int i = tid; i < CIP; i += 256) sbm2[i] = (i < C_IN) ? bm2[i] : 0.f;
    __syncthreads();

    const float xmax = __int_as_float(*xmaxi);
    const float binv = (xmax > 0.f) ? xmax * (1.f / 256.f) : 1.f;

    const int base = blockIdx.x * 512;
    const int lane = tid & 31;

    int e[2], src[2], dstL[2], key[2];
    float2 w[2];
    bool valid[2];
#pragma unroll
    for (int s = 0; s < 2; s++) {
        e[s] = base + 256 * s + tid;
        valid[s] = (e[s] < E);
        src[s] = 0; dstL[s] = 0; key[s] = -1;
        w[s] = make_float2(0.f, 0.f);
        if (valid[s]) {
            src[s]  = srcArr[e[s]];
            dstL[s] = dstArr[e[s]];
            key[s]  = dstL[s];
            w[s]    = wArr[e[s]];
        }
    }

    const float4* A40 = (const float4*)(A + (size_t)dstL[0] * NMSG);
    const float4* A41 = (const float4*)(A + (size_t)dstL[1] * NMSG);
    const uint4*  B80 = (const uint4*)(Bh + (size_t)src[0] * BSTR);
    const uint4*  B81 = (const uint4*)(Bh + (size_t)src[1] * BSTR);
    const float4* WE0 = (const float4*)(sWE);
    const float4* WE1 = (const float4*)(sWE + NMSG);

    u64 m0[CP2], m1[CP2];
#pragma unroll
    for (int p = 0; p < CP2; p++) { m0[p] = 0ull; m1[p] = 0ull; }

#pragma unroll 1
    for (int kq = 0; kq < NMSG / 8; kq++) {      // 25 iterations, 8 k's each
        uint4 br0 = B80[kq];
        uint4 br1 = B81[kq];
        float bf0[8], bf1[8];
        {
            float2 f;
            f = __half22float2(*(const __half2*)&br0.x); bf0[0] = f.x; bf0[1] = f.y;
            f = __half22float2(*(const __half2*)&br0.y); bf0[2] = f.x; bf0[3] = f.y;
            f = __half22float2(*(const __half2*)&br0.z); bf0[4] = f.x; bf0[5] = f.y;
            f = __half22float2(*(const __half2*)&br0.w); bf0[6] = f.x; bf0[7] = f.y;
            f = __half22float2(*(const __half2*)&br1.x); bf1[0] = f.x; bf1[1] = f.y;
            f = __half22float2(*(const __half2*)&br1.y); bf1[2] = f.x; bf1[3] = f.y;
            f = __half22float2(*(const __half2*)&br1.z); bf1[4] = f.x; bf1[5] = f.y;
            f = __half22float2(*(const __half2*)&br1.w); bf1[6] = f.x; bf1[7] = f.y;
        }
#pragma unroll
        for (int sub = 0; sub < 2; sub++) {
            const int kg = kq * 2 + sub;
            float4 a0 = A40[kg];
            float4 a1 = A41[kg];
            float4 u0 = WE0[kg];
            float4 u1 = WE1[kg];
            float h0[4], h1[4];
            h0[0] = fmaxf(fmaf(w[0].x, u0.x, fmaf(w[0].y, u1.x, fmaf(bf0[4*sub+0], binv, a0.x))), 0.f);
            h0[1] = fmaxf(fmaf(w[0].x, u0.y, fmaf(w[0].y, u1.y, fmaf(bf0[4*sub+1], binv, a0.y))), 0.f);
            h0[2] = fmaxf(fmaf(w[0].x, u0.z, fmaf(w[0].y, u1.z, fmaf(bf0[4*sub+2], binv, a0.z))), 0.f);
            h0[3] = fmaxf(fmaf(w[0].x, u0.w, fmaf(w[0].y, u1.w, fmaf(bf0[4*sub+3], binv, a0.w))), 0.f);
            h1[0] = fmaxf(fmaf(w[1].x, u0.x, fmaf(w[1].y, u1.x, fmaf(bf1[4*sub+0], binv, a1.x))), 0.f);
            h1[1] = fmaxf(fmaf(w[1].x, u0.y, fmaf(w[1].y, u1.y, fmaf(bf1[4*sub+1], binv, a1.y))), 0.f);
            h1[2] = fmaxf(fmaf(w[1].x, u0.z, fmaf(w[1].y, u1.z, fmaf(bf1[4*sub+2], binv, a1.z))), 0.f);
            h1[3] = fmaxf(fmaf(w[1].x, u0.w, fmaf(w[1].y, u1.w, fmaf(bf1[4*sub+3], binv, a1.w))), 0.f);
            u64 h0p[4] = { pack2(h0[0]), pack2(h0[1]), pack2(h0[2]), pack2(h0[3]) };
            u64 h1p[4] = { pack2(h1[0]), pack2(h1[1]), pack2(h1[2]), pack2(h1[3]) };

#pragma unroll
            for (int r = 0; r < 4; r++) {
                const float4* row = (const float4*)(sWm2 + (4 * kg + r) * CIP);
#pragma unroll
                for (int j = 0; j < C4; j++) {
                    float4 q = row[j];
                    u64 qlo = pairf(q.x, q.y);
                    u64 qhi = pairf(q.z, q.w);
                    m0[2 * j]     = fma2(h0p[r], qlo, m0[2 * j]);
                    m0[2 * j + 1] = fma2(h0p[r], qhi, m0[2 * j + 1]);
                    m1[2 * j]     = fma2(h1p[r], qlo, m1[2 * j]);
                    m1[2 * j + 1] = fma2(h1p[r], qhi, m1[2 * j + 1]);
                }
            }
        }
    }

    // Per edge set: t = (m + bm2) * (xi - xj), segmented scan, tail atomics
#pragma unroll
    for (int s = 0; s < 2; s++) {
        float t[C_IN];
        {
            const float2* xd2 = (const float2*)(x + (size_t)dstL[s] * C_IN);
            const float2* xs2 = (const float2*)(x + (size_t)src[s]  * C_IN);
            u64* mm = (s == 0) ? m0 : m1;
#pragma unroll
            for (int p = 0; p < C_IN / 2; p++) {
                float2 mp = unpack2(mm[p]);
                float2 xi = xd2[p];
                float2 xj = xs2[p];
                if (RELU_IN) {
                    xi.x = fmaxf(xi.x, 0.f); xi.y = fmaxf(xi.y, 0.f);
                    xj.x = fmaxf(xj.x, 0.f); xj.y = fmaxf(xj.y, 0.f);
                }
                t[2 * p]     = (mp.x + sbm2[2 * p])     * (xi.x - xj.x);
                t[2 * p + 1] = (mp.y + sbm2[2 * p + 1]) * (xi.y - xj.y);
            }
            if (!valid[s]) {
#pragma unroll
                for (int c = 0; c < C_IN; c++) t[c] = 0.f;
            }
        }

        bool pr[5];
#pragma unroll
        for (int r = 0; r < 5; r++) {
            int off = 1 << r;
            int ku = __shfl_up_sync(0xffffffffu, key[s], off);
            pr[r] = (lane >= off) && (ku == key[s]);
        }
#pragma unroll
        for (int r = 0; r < 5; r++) {
            int off = 1 << r;
            bool p = pr[r];
#pragma unroll
            for (int c = 0; c < C_IN; c++) {
                float u = __shfl_up_sync(0xffffffffu, t[c], off);
                if (p) t[c] += u;
            }
        }
        int kn = __shfl_down_sync(0xffffffffu, key[s], 1);
        bool tail = (lane == 31) || (kn != key[s]);
        if (valid[s] && tail) {
            float* tp = Tagg + (size_t)dstL[s] * TSTR;
#pragma unroll
            for (int c = 0; c < C_IN; c++) atomicAdd(tp + c, t[c]);
        }
    }
}

// ---------------------------------------------------------------------------
// Host-side layer driver (C_IN=30 layers)
// ---------------------------------------------------------------------------
template <int C_IN, int C_OUT, bool RELU_IN>
static void run_layer(const float* xin,
                      const float* const* W,   // W1,b1,Wm1,bm1,Wm2,bm2,W2,b2
                      const int* ssrc, const int* sdst, const float2* sw,
                      float* Abuf, __half* Bbuf, float* Tbuf, const int* cnt,
                      const int* xmax_in, int* xmax_out,
                      float* xout,
                      int N, int E) {
    int pg = N * (NMSG / 4);
    if (N * TSTR > pg) pg = N * TSTR;
    precomp_ab_kernel<C_IN, RELU_IN><<<(pg + 255) / 256, 256>>>(
        xin, W[2], W[3], Abuf, Bbuf, xmax_in, Tbuf, N);
    edge_kernel<C_IN, RELU_IN><<<(E + 511) / 512, 256>>>(
        ssrc, sdst, sw, xin, Abuf, Bbuf, W[2], W[4], W[5], xmax_in, Tbuf, E);
    node_finish_kernel<C_IN, C_OUT, RELU_IN><<<(N * C_OUT + 255) / 256, 256>>>(
        xin, W[0], W[1], W[6], W[7], Tbuf, cnt, xout, xmax_out, N);
}

extern "C" void kernel_launch(void* const* d_in, const int* in_sizes, int n_in,
                              void* d_out, int out_size) {
    const float* feat  = (const float*)d_in[0];
    const void*  edges = d_in[1];
    const float* ew    = (const float*)d_in[2];

    const float* P[24];
    for (int i = 0; i < 24; i++) P[i] = (const float*)d_in[3 + i];
    // P[0..7] = layer d, P[8..15] = layer h, P[16..23] = layer o

    int N = in_sizes[0];
    int E = in_sizes[2] / 2;

    float *x0, *x1, *A, *T;
    __half *Bhp;
    int *ssrc, *sdst, *cnt, *xm;
    float2 *sw;
    cudaGetSymbolAddress((void**)&x0,   g_x0);
    cudaGetSymbolAddress((void**)&x1,   g_x1);
    cudaGetSymbolAddress((void**)&A,    g_A);
    cudaGetSymbolAddress((void**)&Bhp,  g_Bh);
    cudaGetSymbolAddress((void**)&T,    g_T);
    cudaGetSymbolAddress((void**)&ssrc, g_ssrc);
    cudaGetSymbolAddress((void**)&sdst, g_sdst);
    cudaGetSymbolAddress((void**)&sw,   g_sw);
    cudaGetSymbolAddress((void**)&cnt,  g_cnt);
    cudaGetSymbolAddress((void**)&xm,   g_xmaxi);

    // Preprocessing: dtype detect + counting sort by dst (parallel scan)
    int nb = (N + 1023) / 1024;
    detect_edges_kernel<<<1, 32>>>((const long long*)edges);
    zero_hist_kernel<<<(N + 255) / 256, 256>>>(N);
    hist_kernel<<<(E + 255) / 256, 256>>>(edges, E);
    scan1_kernel<<<nb, 1024>>>(N);
    scan2_kernel<<<1, 32>>>(nb);
    scan3_kernel<<<nb, 1024>>>(N);
    scatter_kernel<<<(E + 255) / 256, 256>>>(edges, ew, E);

    // d layer: scalar-x edge kernel; node_finish records xmax of relu(x0) -> xm[0]
    zeroT_kernel<<<(N * TSTR + 255) / 256, 256>>>(T, N * TSTR);
    edge_d_kernel<<<(E + 255) / 256, 256>>>(
        ssrc, sdst, sw, feat, P[2], P[3], P[4], P[5], T, E);
    node_finish_kernel<1, 30, false><<<(N * 30 + 255) / 256, 256>>>(
        feat, P[0], P[1], P[6], P[7], T, cnt, x0, xm + 0, N);

    // hidden layers (shared weights) + output layer
    run_layer<30, 30, true>(x0, P + 8,  ssrc, sdst, sw, A, Bhp, T, cnt, xm + 0, xm + 1, x1, N, E);
    run_layer<30, 30, true>(x1, P + 8,  ssrc, sdst, sw, A, Bhp, T, cnt, xm + 1, xm + 2, x0, N, E);
    run_layer<30, 30, true>(x0, P + 8,  ssrc, sdst, sw, A, Bhp, T, cnt, xm + 2, xm + 3, x1, N, E);
    run_layer<30, 1, true>(x1,  P + 16, ssrc, sdst, sw, A, Bhp, T, cnt, xm + 3, nullptr,
                           (float*)d_out, N, E);
}

// round 12
// speedup vs baseline: 2.7193x; 1.2468x over previous
#include <cuda_runtime.h>
#include <cuda_fp16.h>
#include <cstdint>

#define NN      50000
#define NE      800000
#define NMSG    200
#define KP      208           // padded k (13 tiles of 16); A' fp32 & B fp16 row stride
#define TSTR    32            // Tagg row stride (floats)
#define W2KP    216           // Wm2T shared k-stride (halves), bank-clean
#define HSTR    24            // h-tile row stride (halves) = 48B, bank-clean
#define CSTR    36            // C staging row stride (floats)

// ---------------------------------------------------------------------------
// Static device scratch
// ---------------------------------------------------------------------------
__device__ __align__(16) float  g_x0[NN * 30];
__device__ __align__(16) float  g_x1[NN * 30];
__device__ __align__(16) float  g_A [NN * KP];    // A' = (x@Wm1a + bm1) * bs, fp32
__device__ __align__(16) __half g_Bh[NN * KP];    // B  = (x@Wm1b) * bs, fp16
__device__ __align__(16) float  g_T [NN * TSTR];
__device__ int g_is64;
__device__ int g_cnt[NN];
__device__ int g_ofs[NN];
__device__ int g_bsum[64];
__device__ int g_xmaxi[8];     // per-layer max(relu(x)) as float bits (nonneg)
__device__ int g_ssrc[NE];
__device__ int g_sdst[NE];
__device__ __align__(8) float2 g_sw[NE];

// ---------------------------------------------------------------------------
// mma.m16n8k16 f16 x f16 -> f32
// ---------------------------------------------------------------------------
__device__ __forceinline__ void mma16816(float* c,
                                         unsigned a0, unsigned a1, unsigned a2, unsigned a3,
                                         unsigned b0, unsigned b1) {
    asm volatile(
        "mma.sync.aligned.m16n8k16.row.col.f32.f16.f16.f32 "
        "{%0,%1,%2,%3}, {%4,%5,%6,%7}, {%8,%9}, {%0,%1,%2,%3};"
        : "+f"(c[0]), "+f"(c[1]), "+f"(c[2]), "+f"(c[3])
        : "r"(a0), "r"(a1), "r"(a2), "r"(a3), "r"(b0), "r"(b1));
}

// ---------------------------------------------------------------------------
// Edge dtype detection
// ---------------------------------------------------------------------------
__global__ void detect_edges_kernel(const long long* __restrict__ e64) {
    if (threadIdx.x == 0 && blockIdx.x == 0) {
        int ok = 1;
        for (int i = 0; i < 16; i++) {
            long long v = e64[i];
            if (v < 0 || v >= NN) ok = 0;
        }
        g_is64 = ok;
    }
}
__device__ __forceinline__ int load_idx(const void* edges, long long pos, bool is64) {
    if (is64) return (int)((const long long*)edges)[pos];
    return ((const int*)edges)[pos];
}

// ---------------------------------------------------------------------------
// Counting sort by dst (parallel scan)
// ---------------------------------------------------------------------------
__global__ void zero_hist_kernel(int N) {
    int i = blockIdx.x * blockDim.x + threadIdx.x;
    if (i < N) g_cnt[i] = 0;
    if (i < 8) g_xmaxi[i] = 0;
}
__global__ void hist_kernel(const void* __restrict__ edges, int E) {
    int e = blockIdx.x * blockDim.x + threadIdx.x;
    if (e >= E) return;
    bool is64 = (g_is64 != 0);
    atomicAdd(&g_cnt[load_idx(edges, (long long)E + e, is64)], 1);
}
__global__ void scan1_kernel(int N) {
    __shared__ int s[1024];
    int i = blockIdx.x * 1024 + threadIdx.x;
    int v = (i < N) ? g_cnt[i] : 0;
    s[threadIdx.x] = v;
    __syncthreads();
    for (int off = 1; off < 1024; off <<= 1) {
        int t = (threadIdx.x >= (unsigned)off) ? s[threadIdx.x - off] : 0;
        __syncthreads();
        s[threadIdx.x] += t;
        __syncthreads();
    }
    if (i < N) g_ofs[i] = s[threadIdx.x] - v;
    if (threadIdx.x == 1023) g_bsum[blockIdx.x] = s[1023];
}
__global__ void scan2_kernel(int nb) {
    if (threadIdx.x == 0 && blockIdx.x == 0) {
        int acc = 0;
        for (int b = 0; b < nb; b++) { int t = g_bsum[b]; g_bsum[b] = acc; acc += t; }
    }
}
__global__ void scan3_kernel(int N) {
    int i = blockIdx.x * 1024 + threadIdx.x;
    if (i < N) g_ofs[i] += g_bsum[blockIdx.x];
}
__global__ void scatter_kernel(const void* __restrict__ edges,
                               const float* __restrict__ ea, int E) {
    int e = blockIdx.x * blockDim.x + threadIdx.x;
    if (e >= E) return;
    bool is64 = (g_is64 != 0);
    int src = load_idx(edges, e, is64);
    int dst = load_idx(edges, (long long)E + e, is64);
    int p = atomicAdd(&g_ofs[dst], 1);
    g_ssrc[p] = src;
    g_sdst[p] = dst;
    g_sw[p]   = ((const float2*)ea)[e];
}

__global__ void zeroT_kernel(float* __restrict__ T, int n) {
    int i = blockIdx.x * blockDim.x + threadIdx.x;
    if (i < n) T[i] = 0.f;
}

// ---------------------------------------------------------------------------
// Per-node precompute, vectorized (4 k's per thread), PRE-SCALED by bs:
//   A'[n,k] = (relu?(x)·Wm1[0:C,k] + bm1[k]) * bs   (fp32)
//   B [n,k] = (relu?(x)·Wm1[C:2C,k]) * bs           (fp16)
// k >= 200 zero-padded. Also zeroes Tagg.
// ---------------------------------------------------------------------------
template <int C_IN, bool RELU_IN>
__global__ void precomp_ab_kernel(const float* __restrict__ x,
                                  const float* __restrict__ Wm1,
                                  const float* __restrict__ bm1,
                                  float* __restrict__ Ap,
                                  __half* __restrict__ Bh,
                                  const int* __restrict__ xmaxi,
                                  float* __restrict__ Tagg,
                                  int N) {
    int idx = blockIdx.x * blockDim.x + threadIdx.x;
    if (idx < N * TSTR) Tagg[idx] = 0.f;
    if (idx >= N * (KP / 4)) return;
    int n  = idx / (KP / 4);
    int kq = idx - n * (KP / 4);

    if (kq >= NMSG / 4) {   // pad region k in [200,208)
        ((float4*)(Ap + (size_t)n * KP))[kq] = make_float4(0.f, 0.f, 0.f, 0.f);
        __half2 z = __floats2half2_rn(0.f, 0.f);
        __half2* bp = (__half2*)(Bh + (size_t)n * KP + kq * 4);
        bp[0] = z; bp[1] = z;
        return;
    }

    float xmax = __int_as_float(*xmaxi);
    float bs = (xmax > 0.f) ? 256.f / xmax : 1.f;

    float4 a = ((const float4*)bm1)[kq];
    float4 b = make_float4(0.f, 0.f, 0.f, 0.f);
#pragma unroll
    for (int c = 0; c < C_IN; c++) {
        float xv = x[(size_t)n * C_IN + c];
        if (RELU_IN) xv = fmaxf(xv, 0.f);
        float4 wa = ((const float4*)(Wm1 + c * NMSG))[kq];
        float4 wb = ((const float4*)(Wm1 + (C_IN + c) * NMSG))[kq];
        a.x = fmaf(xv, wa.x, a.x); a.y = fmaf(xv, wa.y, a.y);
        a.z = fmaf(xv, wa.z, a.z); a.w = fmaf(xv, wa.w, a.w);
        b.x = fmaf(xv, wb.x, b.x); b.y = fmaf(xv, wb.y, b.y);
        b.z = fmaf(xv, wb.z, b.z); b.w = fmaf(xv, wb.w, b.w);
    }
    a.x *= bs; a.y *= bs; a.z *= bs; a.w *= bs;
    ((float4*)(Ap + (size_t)n * KP))[kq] = a;
    __half2 b01 = __floats2half2_rn(b.x * bs, b.y * bs);
    __half2 b23 = __floats2half2_rn(b.z * bs, b.w * bs);
    __half2* bp = (__half2*)(Bh + (size_t)n * KP + kq * 4);
    bp[0] = b01; bp[1] = b23;
}

// ---------------------------------------------------------------------------
// Node finish: out = b1 + deg*b2 + x@W1 + Tagg@W2; also records max(relu(out))
// ---------------------------------------------------------------------------
template <int C_IN, int C_OUT, bool RELU_IN>
__global__ void node_finish_kernel(const float* __restrict__ x,
                                   const float* __restrict__ W1,
                                   const float* __restrict__ b1,
                                   const float* __restrict__ W2,
                                   const float* __restrict__ b2,
                                   const float* __restrict__ Tagg,
                                   const int* __restrict__ cnt,
                                   float* __restrict__ out,
                                   int* __restrict__ xmax_out,   // nullable
                                   int N) {
    int idx = blockIdx.x * blockDim.x + threadIdx.x;
    float v = 0.f;
    bool inb = (idx < N * C_OUT);
    if (inb) {
        int n  = idx / C_OUT;
        int co = idx - n * C_OUT;
        v = b1[co] + (float)cnt[n] * b2[co];
#pragma unroll
        for (int c = 0; c < C_IN; c++) {
            float xv = x[(size_t)n * C_IN + c];
            if (RELU_IN) xv = fmaxf(xv, 0.f);
            v = fmaf(xv, W1[c * C_OUT + co], v);
            v = fmaf(Tagg[(size_t)n * TSTR + c], W2[c * C_OUT + co], v);
        }
        out[idx] = v;
    }
    if (xmax_out != nullptr) {
        float lv = inb ? fmaxf(v, 0.f) : 0.f;
#pragma unroll
        for (int off = 16; off > 0; off >>= 1)
            lv = fmaxf(lv, __shfl_xor_sync(0xffffffffu, lv, off));
        __shared__ float wmax[8];
        int lane = threadIdx.x & 31, warp = threadIdx.x >> 5;
        if (lane == 0) wmax[warp] = lv;
        __syncthreads();
        if (threadIdx.x == 0) {
            float bm = wmax[0];
#pragma unroll
            for (int i = 1; i < 8; i++) bm = fmaxf(bm, wmax[i]);
            atomicMax(xmax_out, __float_as_int(bm));
        }
    }
}

// ---------------------------------------------------------------------------
// d-layer edge kernel (C_IN=1): scalar t, segmented-scan aggregation
// ---------------------------------------------------------------------------
__global__ void __launch_bounds__(256)
edge_d_kernel(const int* __restrict__ srcArr,
              const int* __restrict__ dstArr,
              const float2* __restrict__ wArr,
              const float* __restrict__ x,
              const float* __restrict__ Wm1,
              const float* __restrict__ bm1,
              const float* __restrict__ Wm2,
              const float* __restrict__ bm2,
              float* __restrict__ Tagg,
              int E) {
    __shared__ __align__(16) float sW0[NMSG], sW1[NMSG], sE0[NMSG], sE1[NMSG];
    __shared__ __align__(16) float sB1[NMSG], sM2[NMSG];
    __shared__ float sbm2s;

    const int tid = threadIdx.x;
    for (int i = tid; i < NMSG; i += 256) {
        sW0[i] = Wm1[0 * NMSG + i];
        sW1[i] = Wm1[1 * NMSG + i];
        sE0[i] = Wm1[2 * NMSG + i];
        sE1[i] = Wm1[3 * NMSG + i];
        sB1[i] = bm1[i];
        sM2[i] = Wm2[i];
    }
    if (tid == 0) sbm2s = bm2[0];
    __syncthreads();

    const int e = blockIdx.x * 256 + tid;
    const bool valid = (e < E);
    const int lane = tid & 31;

    int src = 0, dstL = 0, key = -1;
    float2 w = make_float2(0.f, 0.f);
    if (valid) {
        src  = srcArr[e];
        dstL = dstArr[e];
        key  = dstL;
        w    = wArr[e];
    }
    const float xi = x[dstL];
    const float xj = x[src];

    float m = 0.f;
#pragma unroll 2
    for (int g = 0; g < NMSG / 4; g++) {
        float4 w0 = ((const float4*)sW0)[g];
        float4 w1 = ((const float4*)sW1)[g];
        float4 e0 = ((const float4*)sE0)[g];
        float4 e1 = ((const float4*)sE1)[g];
        float4 bb = ((const float4*)sB1)[g];
        float4 m2 = ((const float4*)sM2)[g];
        float h0 = fmaxf(fmaf(xi, w0.x, fmaf(xj, w1.x, fmaf(w.x, e0.x, fmaf(w.y, e1.x, bb.x)))), 0.f);
        float h1 = fmaxf(fmaf(xi, w0.y, fmaf(xj, w1.y, fmaf(w.x, e0.y, fmaf(w.y, e1.y, bb.y)))), 0.f);
        float h2 = fmaxf(fmaf(xi, w0.z, fmaf(xj, w1.z, fmaf(w.x, e0.z, fmaf(w.y, e1.z, bb.z)))), 0.f);
        float h3 = fmaxf(fmaf(xi, w0.w, fmaf(xj, w1.w, fmaf(w.x, e0.w, fmaf(w.y, e1.w, bb.w)))), 0.f);
        m = fmaf(h0, m2.x, fmaf(h1, m2.y, fmaf(h2, m2.z, fmaf(h3, m2.w, m))));
    }

    float t = valid ? (m + sbm2s) * (xi - xj) : 0.f;

#pragma unroll
    for (int r = 0; r < 5; r++) {
        int off = 1 << r;
        int ku = __shfl_up_sync(0xffffffffu, key, off);
        float tu = __shfl_up_sync(0xffffffffu, t, off);
        if (lane >= off && ku == key) t += tu;
    }
    int kn = __shfl_down_sync(0xffffffffu, key, 1);
    bool tail = (lane == 31) || (kn != key);
    if (valid && tail) atomicAdd(Tagg + (size_t)dstL * TSTR, t);
}

// ---------------------------------------------------------------------------
// Hidden/output edge kernel (C_IN=30) — TENSOR CORE GEMV, split-precision.
// h = h_hi + h_lo (fp16 pair), Wm2 = w_hi + w_lo (fp16 pair).
// C += h_hi*w_hi + h_hi*w_lo + h_lo*w_hi  (3 mmas; lo*lo dropped, ~2^-22).
// Dynamic smem:
//   sWE  [2][208] f32          @ 0      (1664 B)
//   sW2H [32][216] f16         @ 1664   (13824 B)
//   sW2L [32][216] f16         @ 15488  (13824 B)
//   sbm2 [32] f32              @ 29312  (128 B)
//   warpbuf 8 x (32*36) f32    @ 29440  (36864 B)   -> total 66304 B
// ---------------------------------------------------------------------------
#define SM_WE_B    0
#define SM_W2H_B   (416 * 4)                       // 1664
#define SM_W2L_B   (SM_W2H_B + 32 * W2KP * 2)      // 15488
#define SM_BM2_B   (SM_W2L_B + 32 * W2KP * 2)      // 29312
#define SM_WARP_B  (SM_BM2_B + 128)                // 29440
#define SM_TOTAL_B (SM_WARP_B + 8 * 32 * CSTR * 4) // 66304

template <int C_IN, bool RELU_IN>
__global__ void __launch_bounds__(256)
edge_mma_kernel(const int* __restrict__ srcArr,
                const int* __restrict__ dstArr,
                const float2* __restrict__ wArr,
                const float* __restrict__ x,
                const float* __restrict__ Ap,
                const __half* __restrict__ Bh,
                const float* __restrict__ Wm1,
                const float* __restrict__ Wm2,
                const float* __restrict__ bm2,
                const int* __restrict__ xmaxi,
                float* __restrict__ Tagg,
                int E) {
    extern __shared__ char smem[];
    float*  sWE  = (float*)(smem + SM_WE_B);
    __half* sW2H = (__half*)(smem + SM_W2H_B);
    __half* sW2L = (__half*)(smem + SM_W2L_B);
    float*  sbm2 = (float*)(smem + SM_BM2_B);

    const int tid = threadIdx.x;
    for (int i = tid; i < 2 * KP; i += 256) {
        int row = i / KP, k = i - row * KP;
        sWE[i] = (k < NMSG) ? Wm1[2 * C_IN * NMSG + row * NMSG + k] : 0.f;
    }
    for (int i = tid; i < 32 * W2KP; i += 256) {
        int n = i / W2KP, k = i - n * W2KP;
        float v = (n < C_IN && k < NMSG) ? Wm2[k * C_IN + n] : 0.f;
        __half hi = __float2half_rn(v);
        sW2H[i] = hi;
        sW2L[i] = __float2half_rn(v - __half2float(hi));
    }
    if (tid < 32) sbm2[tid] = (tid < C_IN) ? bm2[tid] : 0.f;
    __syncthreads();

    const int lane = tid & 31;
    const int warp = tid >> 5;
    const int gq   = lane >> 2;   // groupID
    const int tg   = lane & 3;    // threadID_in_group
    float*  wb   = (float*)(smem + SM_WARP_B) + warp * (32 * CSTR);
    __half* htH  = (__half*)wb;                  // hi tile: 32 x HSTR (1536 B)
    __half* htL  = htH + 32 * HSTR;              // lo tile: 32 x HSTR (1536 B)

    const float xmax   = __int_as_float(*xmaxi);
    const float inv_bs = (xmax > 0.f) ? xmax * (1.f / 256.f) : 1.f;
    const float bs     = (xmax > 0.f) ? 256.f / xmax : 1.f;

    const int e = blockIdx.x * 256 + warp * 32 + lane;
    const bool valid = (e < E);
    int src = 0, dstL = 0, key = -1;
    float2 w = make_float2(0.f, 0.f);
    if (valid) {
        src  = srcArr[e];
        dstL = dstArr[e];
        key  = dstL;
        w    = wArr[e];
    }
    const float wxs = w.x * bs;
    const float wys = w.y * bs;

    const float*  Arow = Ap + (size_t)dstL * KP;
    const __half* Brow = Bh + (size_t)src  * KP;

    float c[8][4];
#pragma unroll
    for (int i = 0; i < 8; i++)
#pragma unroll
        for (int j = 0; j < 4; j++) c[i][j] = 0.f;

#pragma unroll 1
    for (int kt = 0; kt < KP / 16; kt++) {        // 13 tiles
        const int k0 = kt * 16;

        __align__(16) __half2 hhH[8];
        __align__(16) __half2 hhL[8];
#pragma unroll
        for (int hc = 0; hc < 2; hc++) {
            const int kk = k0 + hc * 8;
            float4 a0 = ((const float4*)(Arow + kk))[0];
            float4 a1 = ((const float4*)(Arow + kk))[1];
            uint4  bv = *((const uint4*)(Brow + kk));
            float4 u00 = ((const float4*)(sWE + kk))[0];
            float4 u01 = ((const float4*)(sWE + kk))[1];
            float4 u10 = ((const float4*)(sWE + KP + kk))[0];
            float4 u11 = ((const float4*)(sWE + KP + kk))[1];
            float2 b0 = __half22float2(*(const __half2*)&bv.x);
            float2 b1 = __half22float2(*(const __half2*)&bv.y);
            float2 b2 = __half22float2(*(const __half2*)&bv.z);
            float2 b3 = __half22float2(*(const __half2*)&bv.w);
            float h[8];
            h[0] = fmaxf(fmaf(wxs, u00.x, fmaf(wys, u10.x, a0.x + b0.x)), 0.f);
            h[1] = fmaxf(fmaf(wxs, u00.y, fmaf(wys, u10.y, a0.y + b0.y)), 0.f);
            h[2] = fmaxf(fmaf(wxs, u00.z, fmaf(wys, u10.z, a0.z + b1.x)), 0.f);
            h[3] = fmaxf(fmaf(wxs, u00.w, fmaf(wys, u10.w, a0.w + b1.y)), 0.f);
            h[4] = fmaxf(fmaf(wxs, u01.x, fmaf(wys, u11.x, a1.x + b2.x)), 0.f);
            h[5] = fmaxf(fmaf(wxs, u01.y, fmaf(wys, u11.y, a1.y + b2.y)), 0.f);
            h[6] = fmaxf(fmaf(wxs, u01.z, fmaf(wys, u11.z, a1.z + b3.x)), 0.f);
            h[7] = fmaxf(fmaf(wxs, u01.w, fmaf(wys, u11.w, a1.w + b3.y)), 0.f);
#pragma unroll
            for (int p = 0; p < 4; p++) {
                __half2 hi = __floats2half2_rn(h[2 * p], h[2 * p + 1]);
                float2 hif = __half22float2(hi);
                __half2 lo = __floats2half2_rn(h[2 * p] - hif.x, h[2 * p + 1] - hif.y);
                hhH[hc * 4 + p] = hi;
                hhL[hc * 4 + p] = lo;
            }
        }
        {
            uint4* hwH = (uint4*)(htH + lane * HSTR);
            hwH[0] = *(const uint4*)&hhH[0];
            hwH[1] = *(const uint4*)&hhH[4];
            uint4* hwL = (uint4*)(htL + lane * HSTR);
            hwL[0] = *(const uint4*)&hhL[0];
            hwL[1] = *(const uint4*)&hhL[4];
        }
        __syncwarp();

        // B frags (hi and lo)
        unsigned bfH[4][2], bfL[4][2];
#pragma unroll
        for (int nt = 0; nt < 4; nt++) {
            const __half* wpH = sW2H + (nt * 8 + gq) * W2KP + k0 + 2 * tg;
            bfH[nt][0] = *(const unsigned*)wpH;
            bfH[nt][1] = *(const unsigned*)(wpH + 8);
            const __half* wpL = sW2L + (nt * 8 + gq) * W2KP + k0 + 2 * tg;
            bfL[nt][0] = *(const unsigned*)wpL;
            bfL[nt][1] = *(const unsigned*)(wpL + 8);
        }
#pragma unroll
        for (int mt = 0; mt < 2; mt++) {
            const __half* hbH = htH + mt * 16 * HSTR;
            unsigned aH0 = *(const unsigned*)(hbH + gq * HSTR + 2 * tg);
            unsigned aH1 = *(const unsigned*)(hbH + (gq + 8) * HSTR + 2 * tg);
            unsigned aH2 = *(const unsigned*)(hbH + gq * HSTR + 2 * tg + 8);
            unsigned aH3 = *(const unsigned*)(hbH + (gq + 8) * HSTR + 2 * tg + 8);
            const __half* hbL = htL + mt * 16 * HSTR;
            unsigned aL0 = *(const unsigned*)(hbL + gq * HSTR + 2 * tg);
            unsigned aL1 = *(const unsigned*)(hbL + (gq + 8) * HSTR + 2 * tg);
            unsigned aL2 = *(const unsigned*)(hbL + gq * HSTR + 2 * tg + 8);
            unsigned aL3 = *(const unsigned*)(hbL + (gq + 8) * HSTR + 2 * tg + 8);
#pragma unroll
            for (int nt = 0; nt < 4; nt++) {
                mma16816(c[mt * 4 + nt], aH0, aH1, aH2, aH3, bfH[nt][0], bfH[nt][1]);
                mma16816(c[mt * 4 + nt], aH0, aH1, aH2, aH3, bfL[nt][0], bfL[nt][1]);
                mma16816(c[mt * 4 + nt], aL0, aL1, aL2, aL3, bfH[nt][0], bfH[nt][1]);
            }
        }
        __syncwarp();
    }

    // Stage C frags to smem: row = edge-in-warp, col = n
#pragma unroll
    for (int mt = 0; mt < 2; mt++)
#pragma unroll
        for (int nt = 0; nt < 4; nt++) {
            float* p = wb + (mt * 16 + gq) * CSTR + nt * 8 + 2 * tg;
            p[0] = c[mt * 4 + nt][0];
            p[1] = c[mt * 4 + nt][1];
            p[8 * CSTR + 0] = c[mt * 4 + nt][2];
            p[8 * CSTR + 1] = c[mt * 4 + nt][3];
        }
    __syncwarp();

    // Per-edge m, t, segmented scan, tail atomics
    float t[C_IN];
    {
        const float* mrow = wb + lane * CSTR;
        const float2* xd2 = (const float2*)(x + (size_t)dstL * C_IN);
        const float2* xs2 = (const float2*)(x + (size_t)src  * C_IN);
#pragma unroll
        for (int p = 0; p < C_IN / 2; p++) {
            float2 xi = xd2[p];
            float2 xj = xs2[p];
            if (RELU_IN) {
                xi.x = fmaxf(xi.x, 0.f); xi.y = fmaxf(xi.y, 0.f);
                xj.x = fmaxf(xj.x, 0.f); xj.y = fmaxf(xj.y, 0.f);
            }
            t[2 * p]     = fmaf(mrow[2 * p],     inv_bs, sbm2[2 * p])     * (xi.x - xj.x);
            t[2 * p + 1] = fmaf(mrow[2 * p + 1], inv_bs, sbm2[2 * p + 1]) * (xi.y - xj.y);
        }
        if (!valid) {
#pragma unroll
            for (int cc = 0; cc < C_IN; cc++) t[cc] = 0.f;
        }
    }

    bool pr[5];
#pragma unroll
    for (int r = 0; r < 5; r++) {
        int off = 1 << r;
        int ku = __shfl_up_sync(0xffffffffu, key, off);
        pr[r] = (lane >= off) && (ku == key);
    }
#pragma unroll
    for (int r = 0; r < 5; r++) {
        int off = 1 << r;
        bool p = pr[r];
#pragma unroll
        for (int cc = 0; cc < C_IN; cc++) {
            float u = __shfl_up_sync(0xffffffffu, t[cc], off);
            if (p) t[cc] += u;
        }
    }
    int kn = __shfl_down_sync(0xffffffffu, key, 1);
    bool tail = (lane == 31) || (kn != key);
    if (valid && tail) {
        float* tp = Tagg + (size_t)dstL * TSTR;
#pragma unroll
        for (int cc = 0; cc < C_IN; cc++) atomicAdd(tp + cc, t[cc]);
    }
}

// ---------------------------------------------------------------------------
// Host-side layer driver (C_IN=30 layers)
// ---------------------------------------------------------------------------
template <int C_IN, int C_OUT, bool RELU_IN>
static void run_layer(const float* xin,
                      const float* const* W,   // W1,b1,Wm1,bm1,Wm2,bm2,W2,b2
                      const int* ssrc, const int* sdst, const float2* sw,
                      float* Abuf, __half* Bbuf, float* Tbuf, const int* cnt,
                      const int* xmax_in, int* xmax_out,
                      float* xout,
                      int N, int E) {
    int pg = N * (KP / 4);
    precomp_ab_kernel<C_IN, RELU_IN><<<(pg + 255) / 256, 256>>>(
        xin, W[2], W[3], Abuf, Bbuf, xmax_in, Tbuf, N);
    cudaFuncSetAttribute(edge_mma_kernel<C_IN, RELU_IN>,
                         cudaFuncAttributeMaxDynamicSharedMemorySize, SM_TOTAL_B);
    edge_mma_kernel<C_IN, RELU_IN><<<(E + 255) / 256, 256, SM_TOTAL_B>>>(
        ssrc, sdst, sw, xin, Abuf, Bbuf, W[2], W[4], W[5], xmax_in, Tbuf, E);
    node_finish_kernel<C_IN, C_OUT, RELU_IN><<<(N * C_OUT + 255) / 256, 256>>>(
        xin, W[0], W[1], W[6], W[7], Tbuf, cnt, xout, xmax_out, N);
}

extern "C" void kernel_launch(void* const* d_in, const int* in_sizes, int n_in,
                              void* d_out, int out_size) {
    const float* feat  = (const float*)d_in[0];
    const void*  edges = d_in[1];
    const float* ew    = (const float*)d_in[2];

    const float* P[24];
    for (int i = 0; i < 24; i++) P[i] = (const float*)d_in[3 + i];
    // P[0..7] = layer d, P[8..15] = layer h, P[16..23] = layer o

    int N = in_sizes[0];
    int E = in_sizes[2] / 2;

    float *x0, *x1, *A, *T;
    __half *Bhp;
    int *ssrc, *sdst, *cnt, *xm;
    float2 *sw;
    cudaGetSymbolAddress((void**)&x0,   g_x0);
    cudaGetSymbolAddress((void**)&x1,   g_x1);
    cudaGetSymbolAddress((void**)&A,    g_A);
    cudaGetSymbolAddress((void**)&Bhp,  g_Bh);
    cudaGetSymbolAddress((void**)&T,    g_T);
    cudaGetSymbolAddress((void**)&ssrc, g_ssrc);
    cudaGetSymbolAddress((void**)&sdst, g_sdst);
    cudaGetSymbolAddress((void**)&sw,   g_sw);
    cudaGetSymbolAddress((void**)&cnt,  g_cnt);
    cudaGetSymbolAddress((void**)&xm,   g_xmaxi);

    // Preprocessing: dtype detect + counting sort by dst (parallel scan)
    int nb = (N + 1023) / 1024;
    detect_edges_kernel<<<1, 32>>>((const long long*)edges);
    zero_hist_kernel<<<(N + 255) / 256, 256>>>(N);
    hist_kernel<<<(E + 255) / 256, 256>>>(edges, E);
    scan1_kernel<<<nb, 1024>>>(N);
    scan2_kernel<<<1, 32>>>(nb);
    scan3_kernel<<<nb, 1024>>>(N);
    scatter_kernel<<<(E + 255) / 256, 256>>>(edges, ew, E);

    // d layer: scalar-x edge kernel; node_finish records xmax of relu(x0) -> xm[0]
    zeroT_kernel<<<(N * TSTR + 255) / 256, 256>>>(T, N * TSTR);
    edge_d_kernel<<<(E + 255) / 256, 256>>>(
        ssrc, sdst, sw, feat, P[2], P[3], P[4], P[5], T, E);
    node_finish_kernel<1, 30, false><<<(N * 30 + 255) / 256, 256>>>(
        feat, P[0], P[1], P[6], P[7], T, cnt, x0, xm + 0, N);

    // hidden layers (shared weights) + output layer
    run_layer<30, 30, true>(x0, P + 8,  ssrc, sdst, sw, A, Bhp, T, cnt, xm + 0, xm + 1, x1, N, E);
    run_layer<30, 30, true>(x1, P + 8,  ssrc, sdst, sw, A, Bhp, T, cnt, xm + 1, xm + 2, x0, N, E);
    run_layer<30, 30, true>(x0, P + 8,  ssrc, sdst, sw, A, Bhp, T, cnt, xm + 2, xm + 3, x1, N, E);
    run_layer<30, 1, true>(x1,  P + 16, ssrc, sdst, sw, A, Bhp, T, cnt, xm + 3, nullptr,
                           (float*)d_out, N, E);
}